// round 3
// baseline (speedup 1.0000x reference)
#include <cuda_runtime.h>
#include <cuda_bf16.h>
#include <math_constants.h>

typedef unsigned long long ull;

#define N_NODES   8192
#define EMBED_DIM 128
#define MARGIN    1.0f
#define PAIR_CAP  (1u << 21)   // 2M slots; expected ~663k positive pairs
#define SROW      132          // padded smem row stride (floats)
#define SMEM_BYTES (2 * 128 * SROW * 4)

// ---------------- device scratch (no allocations allowed) ----------------
__device__ int       g_comm[N_NODES];
__device__ float     g_sqn[N_NODES];
__device__ unsigned  g_minneg[N_NODES];     // float bits of min negative dist
__device__ unsigned  g_paircnt;
__device__ int       g_prow[PAIR_CAP];
__device__ float     g_pdist[PAIR_CAP];
__device__ double    g_total;
__device__ ull       g_valid;

// ---------------- packed f32x2 helpers (Blackwell) ----------------
__device__ __forceinline__ ull pk2(float x, float y) {
    ull r;
    asm("mov.b64 %0, {%1, %2};" : "=l"(r) : "f"(x), "f"(y));
    return r;
}
__device__ __forceinline__ void upk2(float& x, float& y, ull v) {
    asm("mov.b64 {%0, %1}, %2;" : "=f"(x), "=f"(y) : "l"(v));
}
__device__ __forceinline__ void fma2(ull& c, ull a, ull b) {
    asm("fma.rn.f32x2 %0, %1, %2, %3;" : "=l"(c) : "l"(a), "l"(b), "l"(c));
}

// ---------------- kernel 0: dtype probe + convert + init ----------------
// communities may arrive as int64 (reference declares int64) or int32 (jax
// without x64). If int64 little-endian, every high 32-bit word is 0 (values
// are 0..99). Probability of a false positive with int32 data is ~(1/100)^4096.
__global__ void init_kernel(const int* __restrict__ comm_raw) {
    __shared__ int s_or;
    int tid = threadIdx.x;
    if (tid == 0) s_or = 0;
    __syncthreads();
    int acc = 0;
    for (int i = tid; i < N_NODES / 2; i += blockDim.x)
        acc |= comm_raw[2 * i + 1];
    if (acc) atomicOr(&s_or, 1);
    __syncthreads();
    bool is64 = (s_or == 0);
    const long long* c64 = (const long long*)comm_raw;
    for (int i = tid; i < N_NODES; i += blockDim.x) {
        g_comm[i]   = is64 ? (int)c64[i] : comm_raw[i];
        g_minneg[i] = 0x7f800000u;  // +inf
    }
    if (tid == 0) { g_paircnt = 0u; g_total = 0.0; g_valid = 0ull; }
}

// ---------------- kernel 1: squared norms (warp per row) ----------------
__global__ void sqn_kernel(const float* __restrict__ emb) {
    int warp = threadIdx.x >> 5, lane = threadIdx.x & 31;
    int row = blockIdx.x * 8 + warp;
    if (row >= N_NODES) return;
    const float* p = emb + (size_t)row * EMBED_DIM;
    float s = 0.f;
#pragma unroll
    for (int k = lane; k < EMBED_DIM; k += 32) { float v = p[k]; s = fmaf(v, v, s); }
#pragma unroll
    for (int o = 16; o; o >>= 1) s += __shfl_xor_sync(0xffffffffu, s, o);
    if (lane == 0) g_sqn[row] = s;
}

// ---------------- kernel 2: fused Gram / distance / min-neg / positives ----
__global__ __launch_bounds__(256) void gemm_kernel(const float* __restrict__ emb) {
    extern __shared__ float sm[];
    float* As = sm;                 // [k][i], k-major, SROW stride
    float* Bs = sm + 128 * SROW;    // [k][j]
    __shared__ int   s_cr[128], s_cc[128];
    __shared__ float s_qr[128], s_qc[128];
    __shared__ unsigned s_cnt, s_base;

    const int tid = threadIdx.x;
    const int rowBase = blockIdx.y * 128;
    const int colBase = blockIdx.x * 128;

    if (tid < 128) {
        s_cr[tid] = g_comm[rowBase + tid];
        s_qr[tid] = g_sqn[rowBase + tid];
    } else {
        int t = tid - 128;
        s_cc[t] = g_comm[colBase + t];
        s_qc[t] = g_sqn[colBase + t];
    }
    if (tid == 0) s_cnt = 0u;

    // load both tiles transposed (K=128 == EMBED_DIM: single K-slab)
    {
        int r = tid >> 1, half = tid & 1;
        const float4* arow = (const float4*)(emb + (size_t)(rowBase + r) * EMBED_DIM) + half * 16;
        const float4* brow = (const float4*)(emb + (size_t)(colBase + r) * EMBED_DIM) + half * 16;
#pragma unroll
        for (int q = 0; q < 16; q++) {
            float4 va = arow[q];
            float4 vb = brow[q];
            int k = half * 64 + q * 4;
            As[(k + 0) * SROW + r] = va.x; As[(k + 1) * SROW + r] = va.y;
            As[(k + 2) * SROW + r] = va.z; As[(k + 3) * SROW + r] = va.w;
            Bs[(k + 0) * SROW + r] = vb.x; Bs[(k + 1) * SROW + r] = vb.y;
            Bs[(k + 2) * SROW + r] = vb.z; Bs[(k + 3) * SROW + r] = vb.w;
        }
    }
    __syncthreads();

    const int tx = tid & 15;   // 8 cols each
    const int ty = tid >> 4;   // 8 rows each

    ull acc[8][4];
#pragma unroll
    for (int r = 0; r < 8; r++)
#pragma unroll
        for (int c = 0; c < 4; c++) acc[r][c] = 0ull;

#pragma unroll 4
    for (int k = 0; k < 128; k++) {
        const float* ap = As + k * SROW + ty * 8;
        const float* bp = Bs + k * SROW + tx * 8;
        float4 a0 = *(const float4*)ap;
        float4 a1 = *(const float4*)(ap + 4);
        ulonglong2 b01 = *(const ulonglong2*)bp;        // cols 0..3 as 2 pairs
        ulonglong2 b23 = *(const ulonglong2*)(bp + 4);  // cols 4..7
        float ar[8] = {a0.x, a0.y, a0.z, a0.w, a1.x, a1.y, a1.z, a1.w};
#pragma unroll
        for (int rr = 0; rr < 8; rr++) {
            ull a2 = pk2(ar[rr], ar[rr]);
            fma2(acc[rr][0], a2, b01.x);
            fma2(acc[rr][1], a2, b01.y);
            fma2(acc[rr][2], a2, b23.x);
            fma2(acc[rr][3], a2, b23.y);
        }
    }

    // epilogue: dist, per-row min over negatives, positive-pair collection
    float dist[8][8];
    int h = 0;
#pragma unroll
    for (int rr = 0; rr < 8; rr++) {
        const int ri = ty * 8 + rr;
        const float sqr = s_qr[ri];
        const int   cr  = s_cr[ri];
        float rmin = CUDART_INF_F;
#pragma unroll
        for (int cc = 0; cc < 8; cc++) {
            const int ci = tx * 8 + cc;
            float lo, hi;
            upk2(lo, hi, acc[rr][cc >> 1]);
            float dot = (cc & 1) ? hi : lo;
            float d2 = sqr + s_qc[ci] - 2.0f * dot;
            float d = sqrtf(fmaxf(d2, 0.0f));
            dist[rr][cc] = d;
            bool same = (cr == s_cc[ci]);
            if (!same) rmin = fminf(rmin, d);
            else if (rowBase + ri != colBase + ci) h++;
        }
        // reduce min across the 16 tx threads (contiguous half-warp)
        rmin = fminf(rmin, __shfl_xor_sync(0xffffffffu, rmin, 1));
        rmin = fminf(rmin, __shfl_xor_sync(0xffffffffu, rmin, 2));
        rmin = fminf(rmin, __shfl_xor_sync(0xffffffffu, rmin, 4));
        rmin = fminf(rmin, __shfl_xor_sync(0xffffffffu, rmin, 8));
        if (tx == 0 && rmin < CUDART_INF_F)
            atomicMin(&g_minneg[rowBase + ri], __float_as_uint(rmin));
    }

    unsigned lbase = 0u;
    if (h) lbase = atomicAdd(&s_cnt, (unsigned)h);
    __syncthreads();
    if (tid == 0) s_base = s_cnt ? atomicAdd(&g_paircnt, s_cnt) : 0u;
    __syncthreads();

    if (h) {
        unsigned base = s_base + lbase;
        unsigned w = 0;
#pragma unroll
        for (int rr = 0; rr < 8; rr++) {
            const int ri = ty * 8 + rr;
            const int cr = s_cr[ri];
#pragma unroll
            for (int cc = 0; cc < 8; cc++) {
                const int ci = tx * 8 + cc;
                if (cr == s_cc[ci] && (rowBase + ri != colBase + ci)) {
                    unsigned p = base + w;
                    if (p < PAIR_CAP) {
                        g_prow[p]  = rowBase + ri;
                        g_pdist[p] = dist[rr][cc];
                    }
                    w++;
                }
            }
        }
    }
}

// ---------------- kernel 3: hinge over positive pairs ----------------
__global__ void pair_kernel() {
    unsigned n = g_paircnt;
    if (n > PAIR_CAP) n = PAIR_CAP;
    const int tid = threadIdx.x;
    double t = 0.0;
    ull c = 0ull;
    for (unsigned i = blockIdx.x * blockDim.x + tid; i < n; i += gridDim.x * blockDim.x) {
        int r = g_prow[i];
        unsigned mb = g_minneg[r];
        if (mb < 0x7f800000u) {  // has_neg (finite min)
            float mn = __uint_as_float(mb);
            float tl = g_pdist[i] - mn + MARGIN;
            if (tl > 0.0f) t += (double)tl;
            c++;
        }
    }
    __shared__ double st[256];
    __shared__ ull    sc[256];
    st[tid] = t; sc[tid] = c;
    __syncthreads();
    for (int s = 128; s; s >>= 1) {
        if (tid < s) { st[tid] += st[tid + s]; sc[tid] += sc[tid + s]; }
        __syncthreads();
    }
    if (tid == 0) {
        if (st[0] != 0.0) atomicAdd(&g_total, st[0]);
        if (sc[0])        atomicAdd(&g_valid, sc[0]);
    }
}

// ---------------- kernel 4: finalize ----------------
__global__ void final_kernel(float* __restrict__ out) {
    out[0] = g_valid ? (float)(g_total / (double)g_valid) : 0.0f;
}

// ---------------- launch ----------------
extern "C" void kernel_launch(void* const* d_in, const int* in_sizes, int n_in,
                              void* d_out, int out_size) {
    const float* emb  = (const float*)d_in[0];
    const int*   comm = (const int*)d_in[1];
    float*       out  = (float*)d_out;

    init_kernel<<<1, 256>>>(comm);
    sqn_kernel<<<N_NODES / 8, 256>>>(emb);

    cudaFuncSetAttribute(gemm_kernel, cudaFuncAttributeMaxDynamicSharedMemorySize, SMEM_BYTES);
    dim3 grid(N_NODES / 128, N_NODES / 128);
    gemm_kernel<<<grid, 256, SMEM_BYTES>>>(emb);

    pair_kernel<<<256, 256>>>();
    final_kernel<<<1, 1>>>(out);
}

// round 6
// speedup vs baseline: 1.7638x; 1.7638x over previous
#include <cuda_runtime.h>
#include <cuda_bf16.h>
#include <math_constants.h>

typedef unsigned long long ull;

#define N_NODES   8192
#define EMBED_DIM 128
#define MARGIN    1.0f
#define NB        (N_NODES / 128)          // 64 tiles per dim
#define NBLOCKS   (NB * (NB + 1) / 2)      // 2080 upper-triangle tiles
#define PAIR_CAP  (1u << 21)               // 2M packed (row,dist) slots
#define SROW      128                      // smem row stride (floats) — conflict-free by design
#define SMEM_BYTES (2 * 128 * SROW * 4)

// ---------------- device scratch (no allocations allowed) ----------------
__device__ int       g_comm[N_NODES];
__device__ float     g_sqn[N_NODES];
__device__ unsigned  g_minneg[N_NODES];     // float bits of min negative dist
__device__ unsigned  g_paircnt;
__device__ ull       g_pair[PAIR_CAP];      // hi32 = anchor row, lo32 = dist bits
__device__ double    g_total;
__device__ ull       g_valid;

// ---------------- packed f32x2 helpers (Blackwell) ----------------
__device__ __forceinline__ void upk2(float& x, float& y, ull v) {
    asm("mov.b64 {%0, %1}, %2;" : "=f"(x), "=f"(y) : "l"(v));
}
__device__ __forceinline__ ull pk2(float x, float y) {
    ull r;
    asm("mov.b64 %0, {%1, %2};" : "=l"(r) : "f"(x), "f"(y));
    return r;
}
__device__ __forceinline__ void fma2(ull& c, ull a, ull b) {
    asm("fma.rn.f32x2 %0, %1, %2, %3;" : "=l"(c) : "l"(a), "l"(b), "l"(c));
}

// ---------------- kernel 0: dtype probe + convert + init ----------------
__global__ void init_kernel(const int* __restrict__ comm_raw) {
    __shared__ int s_or;
    int tid = threadIdx.x;
    if (tid == 0) s_or = 0;
    __syncthreads();
    int acc = 0;
    for (int i = tid; i < N_NODES / 2; i += blockDim.x)
        acc |= comm_raw[2 * i + 1];
    if (acc) atomicOr(&s_or, 1);
    __syncthreads();
    bool is64 = (s_or == 0);
    const long long* c64 = (const long long*)comm_raw;
    for (int i = tid; i < N_NODES; i += blockDim.x) {
        g_comm[i]   = is64 ? (int)c64[i] : comm_raw[i];
        g_minneg[i] = 0x7f800000u;  // +inf
    }
    if (tid == 0) { g_paircnt = 0u; g_total = 0.0; g_valid = 0ull; }
}

// ---------------- kernel 1: squared norms (warp per row) ----------------
__global__ void sqn_kernel(const float* __restrict__ emb) {
    int warp = threadIdx.x >> 5, lane = threadIdx.x & 31;
    int row = blockIdx.x * 8 + warp;
    if (row >= N_NODES) return;
    const float* p = emb + (size_t)row * EMBED_DIM;
    float s = 0.f;
#pragma unroll
    for (int k = lane; k < EMBED_DIM; k += 32) { float v = p[k]; s = fmaf(v, v, s); }
#pragma unroll
    for (int o = 16; o; o >>= 1) s += __shfl_xor_sync(0xffffffffu, s, o);
    if (lane == 0) g_sqn[row] = s;
}

// ---------------- kernel 2: fused Gram / distance / min-neg / positives ----
// Upper-triangle tiles only; off-diagonal tiles feed both row and column stats.
__global__ __launch_bounds__(256) void gemm_kernel(const float* __restrict__ emb) {
    extern __shared__ float sm[];
    float* As = sm;                 // [k][i], k-major
    float* Bs = sm + 128 * SROW;    // [k][j]
    __shared__ int      s_cr[128], s_cc[128];
    __shared__ float    s_qr[128], s_qc[128];
    __shared__ unsigned s_cmin[128];
    __shared__ unsigned s_cnt, s_base;

    const int tid = threadIdx.x;

    // triangular block decode (row-major over upper triangle)
    int by = 0, rem = blockIdx.x;
    while (rem >= NB - by) { rem -= NB - by; by++; }
    const int bx = by + rem;
    const int rowBase = by * 128;
    const int colBase = bx * 128;
    const bool diag = (bx == by);

    if (tid < 128) {
        s_cr[tid]   = g_comm[rowBase + tid];
        s_qr[tid]   = g_sqn[rowBase + tid];
        s_cmin[tid] = 0x7f800000u;
    } else {
        int t = tid - 128;
        s_cc[t] = g_comm[colBase + t];
        s_qc[t] = g_sqn[colBase + t];
    }
    if (tid == 0) s_cnt = 0u;

    // Tile load, transposed to k-major. Thread t<128 loads A-row t; t>=128 B-row (t-128).
    // STS lanes write consecutive rows at fixed k -> conflict-free.
    {
        int r = tid & 127;
        const float4* src = (const float4*)(emb + (size_t)((tid < 128 ? rowBase : colBase) + r) * EMBED_DIM);
        float* dst = (tid < 128) ? As : Bs;
#pragma unroll
        for (int q = 0; q < 32; q++) {
            float4 v = src[q];
            int k = q * 4;
            dst[(k + 0) * SROW + r] = v.x; dst[(k + 1) * SROW + r] = v.y;
            dst[(k + 2) * SROW + r] = v.z; dst[(k + 3) * SROW + r] = v.w;
        }
    }
    __syncthreads();

    const int tx = tid & 15;   // owns column pairs {tx, tx+16, tx+32, tx+48}
    const int ty = tid >> 4;   // owns rows ty*8 .. ty*8+7

    ull acc[8][4];
#pragma unroll
    for (int r = 0; r < 8; r++)
#pragma unroll
        for (int c = 0; c < 4; c++) acc[r][c] = 0ull;

#pragma unroll 4
    for (int k = 0; k < 128; k++) {
        const float* ap = As + k * SROW + ty * 8;
        const float* bp = Bs + k * SROW;
        // B: four LDS.64, lane word-bank = 2*tx -> conflict-free
        ull b0 = *(const ull*)(bp + 2 * tx);
        ull b1 = *(const ull*)(bp + 2 * tx + 32);
        ull b2 = *(const ull*)(bp + 2 * tx + 64);
        ull b3 = *(const ull*)(bp + 2 * tx + 96);
        // A: two broadcast LDS.128
        float4 a0 = *(const float4*)ap;
        float4 a1 = *(const float4*)(ap + 4);
        float ar[8] = {a0.x, a0.y, a0.z, a0.w, a1.x, a1.y, a1.z, a1.w};
#pragma unroll
        for (int rr = 0; rr < 8; rr++) {
            ull a2 = pk2(ar[rr], ar[rr]);
            fma2(acc[rr][0], a2, b0);
            fma2(acc[rr][1], a2, b1);
            fma2(acc[rr][2], a2, b2);
            fma2(acc[rr][3], a2, b3);
        }
    }

    // ---- epilogue: distances, row-min (and col-min if off-diag), positives ----
    float dist[8][8];
    float cmin[8];
#pragma unroll
    for (int cc = 0; cc < 8; cc++) cmin[cc] = CUDART_INF_F;
    int h = 0;
#pragma unroll
    for (int rr = 0; rr < 8; rr++) {
        const int ri  = ty * 8 + rr;
        const float sqr = s_qr[ri];
        const int   cr  = s_cr[ri];
        float rmin = CUDART_INF_F;
#pragma unroll
        for (int cc = 0; cc < 8; cc++) {
            const int ci = 2 * (tx + 16 * (cc >> 1)) + (cc & 1);
            float lo, hi;
            upk2(lo, hi, acc[rr][cc >> 1]);
            float dot = (cc & 1) ? hi : lo;
            float d2 = sqr + s_qc[ci] - 2.0f * dot;
            float d = sqrtf(fmaxf(d2, 0.0f));
            dist[rr][cc] = d;
            if (cr != s_cc[ci]) {
                rmin = fminf(rmin, d);
                cmin[cc] = fminf(cmin[cc], d);
            } else if (!diag || ri != ci) {
                h += diag ? 1 : 2;
            }
        }
        rmin = fminf(rmin, __shfl_xor_sync(0xffffffffu, rmin, 1));
        rmin = fminf(rmin, __shfl_xor_sync(0xffffffffu, rmin, 2));
        rmin = fminf(rmin, __shfl_xor_sync(0xffffffffu, rmin, 4));
        rmin = fminf(rmin, __shfl_xor_sync(0xffffffffu, rmin, 8));
        if (tx == 0 && rmin < CUDART_INF_F)
            atomicMin(&g_minneg[rowBase + ri], __float_as_uint(rmin));
    }

    if (!diag) {
#pragma unroll
        for (int cc = 0; cc < 8; cc++) {
            if (cmin[cc] < CUDART_INF_F) {
                const int ci = 2 * (tx + 16 * (cc >> 1)) + (cc & 1);
                atomicMin(&s_cmin[ci], __float_as_uint(cmin[cc]));
            }
        }
    }

    unsigned lbase = 0u;
    if (h) lbase = atomicAdd(&s_cnt, (unsigned)h);
    __syncthreads();
    if (tid == 0) s_base = s_cnt ? atomicAdd(&g_paircnt, s_cnt) : 0u;
    if (!diag && tid < 128 && s_cmin[tid] < 0x7f800000u)
        atomicMin(&g_minneg[colBase + tid], s_cmin[tid]);
    __syncthreads();

    if (h) {
        unsigned p = s_base + lbase;
#pragma unroll
        for (int rr = 0; rr < 8; rr++) {
            const int ri = ty * 8 + rr;
            const int cr = s_cr[ri];
#pragma unroll
            for (int cc = 0; cc < 8; cc++) {
                const int ci = 2 * (tx + 16 * (cc >> 1)) + (cc & 1);
                if (cr == s_cc[ci] && (!diag || ri != ci)) {
                    unsigned db = __float_as_uint(dist[rr][cc]);
                    if (p < PAIR_CAP)
                        g_pair[p] = ((ull)(unsigned)(rowBase + ri) << 32) | db;
                    p++;
                    if (!diag) {
                        if (p < PAIR_CAP)
                            g_pair[p] = ((ull)(unsigned)(colBase + ci) << 32) | db;
                        p++;
                    }
                }
            }
        }
    }
}

// ---------------- kernel 3: hinge over positive pairs ----------------
__global__ void pair_kernel() {
    unsigned n = g_paircnt;
    if (n > PAIR_CAP) n = PAIR_CAP;
    const int tid = threadIdx.x;
    double t = 0.0;
    ull c = 0ull;
    for (unsigned i = blockIdx.x * blockDim.x + tid; i < n; i += gridDim.x * blockDim.x) {
        ull pk = g_pair[i];
        int r = (int)(pk >> 32);
        unsigned mb = g_minneg[r];
        if (mb < 0x7f800000u) {  // has_neg
            float mn = __uint_as_float(mb);
            float tl = __uint_as_float((unsigned)pk) - mn + MARGIN;
            if (tl > 0.0f) t += (double)tl;
            c++;
        }
    }
    __shared__ double st[256];
    __shared__ ull    sc[256];
    st[tid] = t; sc[tid] = c;
    __syncthreads();
    for (int s = 128; s; s >>= 1) {
        if (tid < s) { st[tid] += st[tid + s]; sc[tid] += sc[tid + s]; }
        __syncthreads();
    }
    if (tid == 0) {
        if (st[0] != 0.0) atomicAdd(&g_total, st[0]);
        if (sc[0])        atomicAdd(&g_valid, sc[0]);
    }
}

// ---------------- kernel 4: finalize ----------------
__global__ void final_kernel(float* __restrict__ out) {
    out[0] = g_valid ? (float)(g_total / (double)g_valid) : 0.0f;
}

// ---------------- launch ----------------
extern "C" void kernel_launch(void* const* d_in, const int* in_sizes, int n_in,
                              void* d_out, int out_size) {
    const float* emb  = (const float*)d_in[0];
    const int*   comm = (const int*)d_in[1];
    float*       out  = (float*)d_out;

    init_kernel<<<1, 256>>>(comm);
    sqn_kernel<<<N_NODES / 8, 256>>>(emb);

    cudaFuncSetAttribute(gemm_kernel, cudaFuncAttributeMaxDynamicSharedMemorySize, SMEM_BYTES);
    gemm_kernel<<<NBLOCKS, 256, SMEM_BYTES>>>(emb);

    pair_kernel<<<512, 256>>>();
    final_kernel<<<1, 1>>>(out);
}

// round 10
// speedup vs baseline: 2.3620x; 1.3391x over previous
#include <cuda_runtime.h>
#include <cuda_bf16.h>
#include <math_constants.h>
#include <cstdint>

typedef unsigned long long ull;

#define N_NODES   8192
#define EMBED_DIM 128
#define MARGIN    1.0f
#define NB        (N_NODES / 128)
#define NBLOCKS   (NB * (NB + 1) / 2)      // 2080 upper-triangle tiles
#define PAIR_CAP  (1u << 21)
#define TILE_B    (128 * 128 * 2)          // one 128x128 bf16 tile = 32KB
#define SMEM_BYTES (4 * TILE_B + 1024)     // +1KB so tiles can be 1024B-aligned

#define MMA_IDESC 0x8200490u               // kind::f16: F32 acc, bf16 a/b, M=128, N=128
#define INF_BITS  0x7f800000u

// tcgen05 exists only on arch-specific ("a") targets; plain compute_103 PTX
// stage must compile the FFMA2 fallback instead.
#if defined(__CUDA_ARCH__) && (defined(__CUDA_ARCH_FEAT_SM103_ALL) || defined(__CUDA_ARCH_FEAT_SM100_ALL) || defined(__CUDA_ARCH_FEAT_SM101_ALL))
#define HAS_TCGEN05 1
#else
#define HAS_TCGEN05 0
#endif

// ---------------- device scratch ----------------
__device__ int            g_comm[N_NODES];
__device__ float          g_sqn[N_NODES];
__device__ unsigned       g_minneg[N_NODES];     // bits of min negative d^2
__device__ unsigned       g_paircnt;
__device__ ull            g_pair[PAIR_CAP];      // hi32=anchor row, lo32=d^2 bits
__device__ double         g_total;
__device__ ull            g_valid;
__device__ __nv_bfloat16  g_hi[N_NODES * EMBED_DIM];
__device__ __nv_bfloat16  g_lo[N_NODES * EMBED_DIM];

// ---------------- kernel 0: dtype probe + convert + init ----------------
__global__ void init_kernel(const int* __restrict__ comm_raw) {
    __shared__ int s_or;
    int tid = threadIdx.x;
    if (tid == 0) s_or = 0;
    __syncthreads();
    int acc = 0;
    for (int i = tid; i < N_NODES / 2; i += blockDim.x)
        acc |= comm_raw[2 * i + 1];
    if (acc) atomicOr(&s_or, 1);
    __syncthreads();
    bool is64 = (s_or == 0);
    const long long* c64 = (const long long*)comm_raw;
    for (int i = tid; i < N_NODES; i += blockDim.x) {
        g_comm[i]   = is64 ? (int)c64[i] : comm_raw[i];
        g_minneg[i] = INF_BITS;
    }
    if (tid == 0) { g_paircnt = 0u; g_total = 0.0; g_valid = 0ull; }
}

// ---------------- kernel 1: squared norms ----------------
__global__ void sqn_kernel(const float* __restrict__ emb) {
    int warp = threadIdx.x >> 5, lane = threadIdx.x & 31;
    int row = blockIdx.x * 8 + warp;
    if (row >= N_NODES) return;
    const float* p = emb + (size_t)row * EMBED_DIM;
    float s = 0.f;
#pragma unroll
    for (int k = lane; k < EMBED_DIM; k += 32) { float v = p[k]; s = fmaf(v, v, s); }
#pragma unroll
    for (int o = 16; o; o >>= 1) s += __shfl_xor_sync(0xffffffffu, s, o);
    if (lane == 0) g_sqn[row] = s;
}

// ---------------- kernel 1b: bf16 hi/lo split ----------------
__global__ void split_kernel(const float* __restrict__ emb) {
    int i = blockIdx.x * blockDim.x + threadIdx.x;   // one float4 per thread
    float4 v = ((const float4*)emb)[i];
    __nv_bfloat16 h0 = __float2bfloat16(v.x), h1 = __float2bfloat16(v.y);
    __nv_bfloat16 h2 = __float2bfloat16(v.z), h3 = __float2bfloat16(v.w);
    __nv_bfloat16 l0 = __float2bfloat16(v.x - __bfloat162float(h0));
    __nv_bfloat16 l1 = __float2bfloat16(v.y - __bfloat162float(h1));
    __nv_bfloat16 l2 = __float2bfloat16(v.z - __bfloat162float(h2));
    __nv_bfloat16 l3 = __float2bfloat16(v.w - __bfloat162float(h3));
    ((__nv_bfloat162*)g_hi)[2 * i]     = __nv_bfloat162(h0, h1);
    ((__nv_bfloat162*)g_hi)[2 * i + 1] = __nv_bfloat162(h2, h3);
    ((__nv_bfloat162*)g_lo)[2 * i]     = __nv_bfloat162(l0, l1);
    ((__nv_bfloat162*)g_lo)[2 * i + 1] = __nv_bfloat162(l2, l3);
}

#if HAS_TCGEN05
// ================= tcgen05 helpers (sm_103a targets only) =================
__device__ __forceinline__ uint32_t smem_u32(const void* p) {
    uint32_t a;
    asm("{ .reg .u64 t; cvta.to.shared.u64 t, %1; cvt.u32.u64 %0, t; }" : "=r"(a) : "l"(p));
    return a;
}
__device__ __forceinline__ uint32_t elect_one() {
    uint32_t p;
    asm volatile("{ .reg .pred p; elect.sync _|p, 0xFFFFFFFF; selp.b32 %0, 1, 0, p; }" : "=r"(p));
    return p;
}
#define TC_ALLOC(sm, n)   asm volatile("tcgen05.alloc.cta_group::1.sync.aligned.shared::cta.b32 [%0], %1;" :: "r"(sm), "r"(n) : "memory")
#define TC_DEALLOC(t, n)  asm volatile("tcgen05.dealloc.cta_group::1.sync.aligned.b32 %0, %1;" :: "r"(t), "r"(n))
#define TC_RELINQ()       asm volatile("tcgen05.relinquish_alloc_permit.cta_group::1.sync.aligned;")
#define TC_COMMIT(mb)     asm volatile("tcgen05.commit.cta_group::1.mbarrier::arrive::one.shared::cluster.b64 [%0];" :: "r"(mb) : "memory")
#define TC_WAIT_LD()      asm volatile("tcgen05.wait::ld.sync.aligned;" ::: "memory")
#define TC_FENCE_AFTER()  asm volatile("tcgen05.fence::after_thread_sync;" ::: "memory")
#define MB_INIT(mb, n)    asm volatile("mbarrier.init.shared.b64 [%0], %1;" :: "r"(mb), "r"(n) : "memory")
#define FENCE_ASYNC()     asm volatile("fence.proxy.async.shared::cta;" ::: "memory")

__device__ __forceinline__ void mbar_wait0(uint32_t mb) {
    asm volatile(
        "{\n\t.reg .pred P1;\n\t"
        "WL_%=:\n\t"
        "mbarrier.try_wait.parity.acquire.cta.shared::cta.b64 P1, [%0], 0, 0x989680;\n\t"
        "@P1 bra.uni WD_%=;\n\t"
        "bra.uni WL_%=;\n\t"
        "WD_%=:\n\t}"
        :: "r"(mb) : "memory");
}
__device__ __forceinline__ void mma_f16_ss(uint32_t d, uint64_t a, uint64_t b, uint32_t idesc, uint32_t acc) {
    asm volatile(
        "{\n\t.reg .pred p;\n\tsetp.ne.u32 p, %5, 0;\n\t"
        "tcgen05.mma.cta_group::1.kind::f16 [%0], %1, %2, %3, {%4, %4, %4, %4}, p;\n\t}"
        :: "r"(d), "l"(a), "l"(b), "r"(idesc), "r"(0u), "r"(acc) : "memory");
}
#define LDTM_X32(r, ta) \
    asm volatile("tcgen05.ld.sync.aligned.32x32b.x32.b32 " \
        "{%0,%1,%2,%3,%4,%5,%6,%7,%8,%9,%10,%11,%12,%13,%14,%15," \
        "%16,%17,%18,%19,%20,%21,%22,%23,%24,%25,%26,%27,%28,%29,%30,%31}, [%32];" \
        : "=r"((r)[0]),"=r"((r)[1]),"=r"((r)[2]),"=r"((r)[3]),"=r"((r)[4]),"=r"((r)[5]),"=r"((r)[6]),"=r"((r)[7]), \
          "=r"((r)[8]),"=r"((r)[9]),"=r"((r)[10]),"=r"((r)[11]),"=r"((r)[12]),"=r"((r)[13]),"=r"((r)[14]),"=r"((r)[15]), \
          "=r"((r)[16]),"=r"((r)[17]),"=r"((r)[18]),"=r"((r)[19]),"=r"((r)[20]),"=r"((r)[21]),"=r"((r)[22]),"=r"((r)[23]), \
          "=r"((r)[24]),"=r"((r)[25]),"=r"((r)[26]),"=r"((r)[27]),"=r"((r)[28]),"=r"((r)[29]),"=r"((r)[30]),"=r"((r)[31]) \
        : "r"(ta))

// SW128 K-major descriptor base: layout=SW128, version=1(Blackwell), SBO=64, LBO=1
static constexpr uint64_t DESC_BASE =
    (uint64_t(2) << 61) | (uint64_t(1) << 46) | (uint64_t(64) << 32) | (uint64_t(1) << 16);
__device__ __forceinline__ uint64_t make_desc(uint32_t addr) {
    return DESC_BASE | ((uint64_t)(addr >> 4) & 0x3FFF);
}

// tile loader: global bf16 -> blocked SW128 atom layout
// atom = 8 rows x 64 bf16 (1024B); atom_offset = atom_row + atom_col*16
// dst MUST be 1024B-aligned (absolute-address swizzle).
__device__ __forceinline__ void load_tile(const __nv_bfloat16* __restrict__ src,
                                          char* dst, int nodeBase, int tid) {
#pragma unroll
    for (int it = 0; it < 8; it++) {
        int ch = tid + 256 * it;            // 2048 chunks of 16B
        int r = ch >> 4, q = ch & 15;
        uint4 v = *(const uint4*)(src + (size_t)(nodeBase + r) * EMBED_DIM + q * 8);
        int bo = ((r >> 3) + ((q >> 3) << 4)) * 1024 + (r & 7) * 128 + (q & 7) * 16;
        *(uint4*)(dst + (bo ^ ((bo >> 3) & 0x70))) = v;
    }
}
#else
// ================= packed f32x2 helpers (fallback path) =================
__device__ __forceinline__ void upk2f(float& x, float& y, ull v) {
    asm("mov.b64 {%0, %1}, %2;" : "=f"(x), "=f"(y) : "l"(v));
}
__device__ __forceinline__ ull pk2f(float x, float y) {
    ull r;
    asm("mov.b64 %0, {%1, %2};" : "=l"(r) : "f"(x), "f"(y));
    return r;
}
__device__ __forceinline__ void fma2f(ull& c, ull a, ull b) {
    asm("fma.rn.f32x2 %0, %1, %2, %3;" : "=l"(c) : "l"(a), "l"(b), "l"(c));
}
#endif

// ---------------- kernel 2: fused Gram / d2 / min-neg / positives ----------
__global__ __launch_bounds__(256, 1) void gemm_kernel(const float* __restrict__ emb) {
    __shared__ int      s_cr[128], s_cc[128];
    __shared__ float    s_qr[128], s_qc[128];
    __shared__ unsigned s_cmin[128];
    __shared__ unsigned s_cnt, s_base;

    const int tid = threadIdx.x;

    // triangular block decode (row-major over upper triangle)
    int by = 0, rem = blockIdx.x;
    while (rem >= NB - by) { rem -= NB - by; by++; }
    const int bx = by + rem;
    const int rowBase = by * 128;
    const int colBase = bx * 128;
    const bool diag = (bx == by);

#if HAS_TCGEN05
    extern __shared__ char smraw[];
    // SW128 swizzle depends on absolute address bits [9:7] — tiles must sit on
    // a 1024B boundary (the R8 3.8e-2 error was a misaligned dynamic-smem base).
    char* sm = (char*)(((uintptr_t)smraw + 1023) & ~(uintptr_t)1023);
    char* Ahi = sm;
    char* Alo = sm + TILE_B;
    char* Bhi = sm + 2 * TILE_B;
    char* Blo = sm + 3 * TILE_B;

    __shared__ unsigned s_rmin[128];
    __shared__ uint32_t s_tmem;
    __shared__ ull      s_mbar;

    const int w    = tid >> 5;
    const int lane = tid & 31;
    const uint32_t mbar_addr = smem_u32(&s_mbar);
    const uint32_t tptr_addr = smem_u32(&s_tmem);

    if (w == 0) TC_ALLOC(tptr_addr, 128);
    if (tid == 0) { MB_INIT(mbar_addr, 1); s_cnt = 0u; }

    if (tid < 128) {
        s_cr[tid]   = g_comm[rowBase + tid];
        s_qr[tid]   = g_sqn[rowBase + tid];
        s_rmin[tid] = INF_BITS;
    } else {
        int t = tid - 128;
        s_cc[t]   = g_comm[colBase + t];
        s_qc[t]   = g_sqn[colBase + t];
        s_cmin[t] = INF_BITS;
    }

    load_tile(g_hi, Ahi, rowBase, tid);
    load_tile(g_lo, Alo, rowBase, tid);
    if (!diag) {
        load_tile(g_hi, Bhi, colBase, tid);
        load_tile(g_lo, Blo, colBase, tid);
    }
    FENCE_ASYNC();
    __syncthreads();

    uint32_t tmem = s_tmem;
    if (w == 0) TC_RELINQ();

    if (w == 0 && elect_one()) {
        uint32_t ahi = smem_u32(Ahi), alo = smem_u32(Alo);
        uint32_t bhi = diag ? ahi : smem_u32(Bhi);
        uint32_t blo = diag ? alo : smem_u32(Blo);
        uint64_t ab[3] = { make_desc(ahi), make_desc(ahi), make_desc(alo) };
        uint64_t bb[3] = { make_desc(bhi), make_desc(blo), make_desc(bhi) };
        uint32_t acc = 0;
#pragma unroll
        for (int t = 0; t < 3; t++) {
#pragma unroll
            for (int ks = 0; ks < 8; ks++) {
                uint64_t ko = (ks < 4) ? (uint64_t)(2 * ks) : (uint64_t)(1024 + 2 * (ks - 4));
                mma_f16_ss(tmem, ab[t] + ko, bb[t] + ko, MMA_IDESC, acc);
                acc = 1;
            }
        }
        TC_COMMIT(mbar_addr);
    }

    mbar_wait0(mbar_addr);
    TC_FENCE_AFTER();

    // epilogue: warp w -> rows (w&3)*32.., cols (w>>2)*64..
    const int rl    = (w & 3) * 32 + lane;
    const int cbase = (w >> 2) * 64;
    const uint32_t warp_off = (uint32_t)(w & 3) << 21;

    uint32_t du[64];
    LDTM_X32(du,      tmem + warp_off + cbase);
    LDTM_X32(du + 32, tmem + warp_off + cbase + 32);
    TC_WAIT_LD();

    const float sqr = s_qr[rl];
    const int   cr  = s_cr[rl];
    float rmin2 = CUDART_INF_F;
    ull nmask = 0ull, pmask = 0ull;
#pragma unroll
    for (int j = 0; j < 64; j++) {
        const int ci = cbase + j;
        float d2 = fmaxf(sqr + s_qc[ci] - 2.0f * __uint_as_float(du[j]), 0.0f);
        du[j] = __float_as_uint(d2);
        if (cr != s_cc[ci]) {
            nmask |= 1ull << j;
            rmin2 = fminf(rmin2, d2);
        } else if (!diag || rl != ci) {
            pmask |= 1ull << j;
        }
    }
    if (rmin2 < CUDART_INF_F) atomicMin(&s_rmin[rl], __float_as_uint(rmin2));

    if (!diag) {
#pragma unroll
        for (int j = 0; j < 64; j++) {
            float v = (nmask >> j) & 1 ? __uint_as_float(du[j]) : CUDART_INF_F;
            v = fminf(v, __shfl_xor_sync(0xffffffffu, v, 1));
            v = fminf(v, __shfl_xor_sync(0xffffffffu, v, 2));
            v = fminf(v, __shfl_xor_sync(0xffffffffu, v, 4));
            v = fminf(v, __shfl_xor_sync(0xffffffffu, v, 8));
            v = fminf(v, __shfl_xor_sync(0xffffffffu, v, 16));
            if (lane == 0 && v < CUDART_INF_F)
                atomicMin(&s_cmin[cbase + j], __float_as_uint(v));
        }
    }

    int h = __popcll(pmask);
    if (!diag) h *= 2;
    unsigned lbase = 0u;
    if (h) lbase = atomicAdd(&s_cnt, (unsigned)h);
    __syncthreads();

    if (tid == 0) s_base = s_cnt ? atomicAdd(&g_paircnt, s_cnt) : 0u;
    if (tid < 128 && s_rmin[tid] != INF_BITS)
        atomicMin(&g_minneg[rowBase + tid], s_rmin[tid]);
    if (!diag && tid >= 128 && s_cmin[tid - 128] != INF_BITS)
        atomicMin(&g_minneg[colBase + tid - 128], s_cmin[tid - 128]);
    __syncthreads();

    if (h) {
        unsigned p = s_base + lbase;
        ull m = pmask;
        while (m) {
            int j = __ffsll((long long)m) - 1;
            m &= m - 1;
            unsigned db = du[j];
            if (p < PAIR_CAP) g_pair[p] = ((ull)(unsigned)(rowBase + rl) << 32) | db;
            p++;
            if (!diag) {
                if (p < PAIR_CAP) g_pair[p] = ((ull)(unsigned)(colBase + cbase + j) << 32) | db;
                p++;
            }
        }
    }

    __syncthreads();
    if (w == 0) TC_DEALLOC(tmem, 128);

#else  // ---------------- FFMA2 fallback body (R3-proven, d2 domain) --------
    extern __shared__ float smf[];
    float* As = smf;                 // [k][i], k-major, stride 128
    float* Bs = smf + 128 * 128;     // [k][j]

    if (tid < 128) {
        s_cr[tid] = g_comm[rowBase + tid];
        s_qr[tid] = g_sqn[rowBase + tid];
        s_cmin[tid] = INF_BITS;
    } else {
        int t = tid - 128;
        s_cc[t] = g_comm[colBase + t];
        s_qc[t] = g_sqn[colBase + t];
    }
    if (tid == 0) s_cnt = 0u;

    {
        int r = tid & 127;
        const float4* src = (const float4*)(emb + (size_t)((tid < 128 ? rowBase : colBase) + r) * EMBED_DIM);
        float* dst = (tid < 128) ? As : Bs;
#pragma unroll
        for (int q = 0; q < 32; q++) {
            float4 v = src[q];
            int k = q * 4;
            dst[(k + 0) * 128 + r] = v.x; dst[(k + 1) * 128 + r] = v.y;
            dst[(k + 2) * 128 + r] = v.z; dst[(k + 3) * 128 + r] = v.w;
        }
    }
    __syncthreads();

    const int tx = tid & 15;
    const int ty = tid >> 4;

    ull acc[8][4];
#pragma unroll
    for (int r = 0; r < 8; r++)
#pragma unroll
        for (int c = 0; c < 4; c++) acc[r][c] = 0ull;

#pragma unroll 4
    for (int k = 0; k < 128; k++) {
        const float* ap = As + k * 128 + ty * 8;
        const float* bp = Bs + k * 128;
        ull b0 = *(const ull*)(bp + 2 * tx);
        ull b1 = *(const ull*)(bp + 2 * tx + 32);
        ull b2 = *(const ull*)(bp + 2 * tx + 64);
        ull b3 = *(const ull*)(bp + 2 * tx + 96);
        float4 a0 = *(const float4*)ap;
        float4 a1 = *(const float4*)(ap + 4);
        float ar[8] = {a0.x, a0.y, a0.z, a0.w, a1.x, a1.y, a1.z, a1.w};
#pragma unroll
        for (int rr = 0; rr < 8; rr++) {
            ull a2 = pk2f(ar[rr], ar[rr]);
            fma2f(acc[rr][0], a2, b0);
            fma2f(acc[rr][1], a2, b1);
            fma2f(acc[rr][2], a2, b2);
            fma2f(acc[rr][3], a2, b3);
        }
    }

    float dist[8][8];
    float cmin[8];
#pragma unroll
    for (int cc = 0; cc < 8; cc++) cmin[cc] = CUDART_INF_F;
    int h = 0;
#pragma unroll
    for (int rr = 0; rr < 8; rr++) {
        const int ri  = ty * 8 + rr;
        const float sqr = s_qr[ri];
        const int   cr  = s_cr[ri];
        float rmin = CUDART_INF_F;
#pragma unroll
        for (int cc = 0; cc < 8; cc++) {
            const int ci = 2 * (tx + 16 * (cc >> 1)) + (cc & 1);
            float lo, hi;
            upk2f(lo, hi, acc[rr][cc >> 1]);
            float dot = (cc & 1) ? hi : lo;
            float d2 = fmaxf(sqr + s_qc[ci] - 2.0f * dot, 0.0f);
            dist[rr][cc] = d2;
            if (cr != s_cc[ci]) {
                rmin = fminf(rmin, d2);
                cmin[cc] = fminf(cmin[cc], d2);
            } else if (!diag || ri != ci) {
                h += diag ? 1 : 2;
            }
        }
        rmin = fminf(rmin, __shfl_xor_sync(0xffffffffu, rmin, 1));
        rmin = fminf(rmin, __shfl_xor_sync(0xffffffffu, rmin, 2));
        rmin = fminf(rmin, __shfl_xor_sync(0xffffffffu, rmin, 4));
        rmin = fminf(rmin, __shfl_xor_sync(0xffffffffu, rmin, 8));
        if (tx == 0 && rmin < CUDART_INF_F)
            atomicMin(&g_minneg[rowBase + ri], __float_as_uint(rmin));
    }

    if (!diag) {
#pragma unroll
        for (int cc = 0; cc < 8; cc++) {
            if (cmin[cc] < CUDART_INF_F) {
                const int ci = 2 * (tx + 16 * (cc >> 1)) + (cc & 1);
                atomicMin(&s_cmin[ci], __float_as_uint(cmin[cc]));
            }
        }
    }

    unsigned lbase = 0u;
    if (h) lbase = atomicAdd(&s_cnt, (unsigned)h);
    __syncthreads();
    if (tid == 0) s_base = s_cnt ? atomicAdd(&g_paircnt, s_cnt) : 0u;
    if (!diag && tid < 128 && s_cmin[tid] != INF_BITS)
        atomicMin(&g_minneg[colBase + tid], s_cmin[tid]);
    __syncthreads();

    if (h) {
        unsigned p = s_base + lbase;
#pragma unroll
        for (int rr = 0; rr < 8; rr++) {
            const int ri = ty * 8 + rr;
            const int cr = s_cr[ri];
#pragma unroll
            for (int cc = 0; cc < 8; cc++) {
                const int ci = 2 * (tx + 16 * (cc >> 1)) + (cc & 1);
                if (cr == s_cc[ci] && (!diag || ri != ci)) {
                    unsigned db = __float_as_uint(dist[rr][cc]);
                    if (p < PAIR_CAP)
                        g_pair[p] = ((ull)(unsigned)(rowBase + ri) << 32) | db;
                    p++;
                    if (!diag) {
                        if (p < PAIR_CAP)
                            g_pair[p] = ((ull)(unsigned)(colBase + ci) << 32) | db;
                        p++;
                    }
                }
            }
        }
    }
#endif
}

// ---------------- kernel 3: hinge over positive pairs (d2 -> d) ------------
__global__ void pair_kernel() {
    unsigned n = g_paircnt;
    if (n > PAIR_CAP) n = PAIR_CAP;
    const int tid = threadIdx.x;
    double t = 0.0;
    ull c = 0ull;
    for (unsigned i = blockIdx.x * blockDim.x + tid; i < n; i += gridDim.x * blockDim.x) {
        ull pk = g_pair[i];
        int r = (int)(pk >> 32);
        unsigned mb = g_minneg[r];
        if (mb < INF_BITS) {  // has_neg
            float d  = sqrtf(__uint_as_float((unsigned)pk));
            float mn = sqrtf(__uint_as_float(mb));
            float tl = d - mn + MARGIN;
            if (tl > 0.0f) t += (double)tl;
            c++;
        }
    }
    __shared__ double st[256];
    __shared__ ull    sc[256];
    st[tid] = t; sc[tid] = c;
    __syncthreads();
    for (int s = 128; s; s >>= 1) {
        if (tid < s) { st[tid] += st[tid + s]; sc[tid] += sc[tid + s]; }
        __syncthreads();
    }
    if (tid == 0) {
        if (st[0] != 0.0) atomicAdd(&g_total, st[0]);
        if (sc[0])        atomicAdd(&g_valid, sc[0]);
    }
}

// ---------------- kernel 4: finalize ----------------
__global__ void final_kernel(float* __restrict__ out) {
    out[0] = g_valid ? (float)(g_total / (double)g_valid) : 0.0f;
}

// ---------------- launch ----------------
extern "C" void kernel_launch(void* const* d_in, const int* in_sizes, int n_in,
                              void* d_out, int out_size) {
    const float* emb  = (const float*)d_in[0];
    const int*   comm = (const int*)d_in[1];
    float*       out  = (float*)d_out;

    init_kernel<<<1, 256>>>(comm);
    sqn_kernel<<<N_NODES / 8, 256>>>(emb);
    split_kernel<<<(N_NODES * EMBED_DIM / 4) / 256, 256>>>(emb);

    cudaFuncSetAttribute(gemm_kernel, cudaFuncAttributeMaxDynamicSharedMemorySize, SMEM_BYTES);
    gemm_kernel<<<NBLOCKS, 256, SMEM_BYTES>>>(emb);

    pair_kernel<<<512, 256>>>();
    final_kernel<<<1, 1>>>(out);
}

// round 12
// speedup vs baseline: 2.5082x; 1.0619x over previous
#include <cuda_runtime.h>
#include <cuda_bf16.h>
#include <math_constants.h>
#include <cstdint>

typedef unsigned long long ull;

#define N_NODES   8192
#define EMBED_DIM 128
#define MARGIN    1.0f
#define NB        (N_NODES / 128)
#define NBLOCKS   (NB * (NB + 1) / 2)      // 2080 upper-triangle tiles
#define PAIR_CAP  (1u << 21)
#define TILE_B    (128 * 128 * 2)          // one 128x128 bf16 tile = 32KB
#define SMEM_BYTES (2 * TILE_B + 1024)     // B_hi + B_lo + alignment slack = 66560

#define MMA_IDESC 0x8200490u               // kind::f16: F32 acc, bf16 a/b, M=128, N=128
#define INF_BITS  0x7f800000u
#define TMEM_A_HI 0
#define TMEM_A_LO 64
#define TMEM_D    128
#define TMEM_COLS 256

#if defined(__CUDA_ARCH__) && (defined(__CUDA_ARCH_FEAT_SM103_ALL) || defined(__CUDA_ARCH_FEAT_SM100_ALL) || defined(__CUDA_ARCH_FEAT_SM101_ALL))
#define HAS_TCGEN05 1
#else
#define HAS_TCGEN05 0
#endif

// ---------------- device scratch ----------------
__device__ int            g_comm[N_NODES];
__device__ float          g_sqn[N_NODES];
__device__ unsigned       g_minneg[N_NODES];     // bits of min negative d^2
__device__ unsigned       g_paircnt;
__device__ ull            g_pair[PAIR_CAP];      // hi32=anchor row, lo32=d^2 bits
__device__ double         g_total;
__device__ ull            g_valid;
__device__ __nv_bfloat16  g_hi[N_NODES * EMBED_DIM];
__device__ __nv_bfloat16  g_lo[N_NODES * EMBED_DIM];

// ---------------- kernel 0: dtype probe + convert + init ----------------
__global__ void init_kernel(const int* __restrict__ comm_raw) {
    __shared__ int s_or;
    int tid = threadIdx.x;
    if (tid == 0) s_or = 0;
    __syncthreads();
    int acc = 0;
    for (int i = tid; i < N_NODES / 2; i += blockDim.x)
        acc |= comm_raw[2 * i + 1];
    if (acc) atomicOr(&s_or, 1);
    __syncthreads();
    bool is64 = (s_or == 0);
    const long long* c64 = (const long long*)comm_raw;
    for (int i = tid; i < N_NODES; i += blockDim.x) {
        g_comm[i]   = is64 ? (int)c64[i] : comm_raw[i];
        g_minneg[i] = INF_BITS;
    }
    if (tid == 0) { g_paircnt = 0u; g_total = 0.0; g_valid = 0ull; }
}

// ---------------- kernel 1: squared norms ----------------
__global__ void sqn_kernel(const float* __restrict__ emb) {
    int warp = threadIdx.x >> 5, lane = threadIdx.x & 31;
    int row = blockIdx.x * 8 + warp;
    if (row >= N_NODES) return;
    const float* p = emb + (size_t)row * EMBED_DIM;
    float s = 0.f;
#pragma unroll
    for (int k = lane; k < EMBED_DIM; k += 32) { float v = p[k]; s = fmaf(v, v, s); }
#pragma unroll
    for (int o = 16; o; o >>= 1) s += __shfl_xor_sync(0xffffffffu, s, o);
    if (lane == 0) g_sqn[row] = s;
}

// ---------------- kernel 1b: bf16 hi/lo split ----------------
__global__ void split_kernel(const float* __restrict__ emb) {
    int i = blockIdx.x * blockDim.x + threadIdx.x;   // one float4 per thread
    float4 v = ((const float4*)emb)[i];
    __nv_bfloat16 h0 = __float2bfloat16(v.x), h1 = __float2bfloat16(v.y);
    __nv_bfloat16 h2 = __float2bfloat16(v.z), h3 = __float2bfloat16(v.w);
    __nv_bfloat16 l0 = __float2bfloat16(v.x - __bfloat162float(h0));
    __nv_bfloat16 l1 = __float2bfloat16(v.y - __bfloat162float(h1));
    __nv_bfloat16 l2 = __float2bfloat16(v.z - __bfloat162float(h2));
    __nv_bfloat16 l3 = __float2bfloat16(v.w - __bfloat162float(h3));
    ((__nv_bfloat162*)g_hi)[2 * i]     = __nv_bfloat162(h0, h1);
    ((__nv_bfloat162*)g_hi)[2 * i + 1] = __nv_bfloat162(h2, h3);
    ((__nv_bfloat162*)g_lo)[2 * i]     = __nv_bfloat162(l0, l1);
    ((__nv_bfloat162*)g_lo)[2 * i + 1] = __nv_bfloat162(l2, l3);
}

#if HAS_TCGEN05
// ================= tcgen05 helpers (sm_103a targets only) =================
__device__ __forceinline__ uint32_t smem_u32(const void* p) {
    uint32_t a;
    asm("{ .reg .u64 t; cvta.to.shared.u64 t, %1; cvt.u32.u64 %0, t; }" : "=r"(a) : "l"(p));
    return a;
}
__device__ __forceinline__ uint32_t elect_one() {
    uint32_t p;
    asm volatile("{ .reg .pred p; elect.sync _|p, 0xFFFFFFFF; selp.b32 %0, 1, 0, p; }" : "=r"(p));
    return p;
}
#define TC_ALLOC(sm, n)   asm volatile("tcgen05.alloc.cta_group::1.sync.aligned.shared::cta.b32 [%0], %1;" :: "r"(sm), "r"(n) : "memory")
#define TC_DEALLOC(t, n)  asm volatile("tcgen05.dealloc.cta_group::1.sync.aligned.b32 %0, %1;" :: "r"(t), "r"(n))
#define TC_RELINQ()       asm volatile("tcgen05.relinquish_alloc_permit.cta_group::1.sync.aligned;")
#define TC_COMMIT(mb)     asm volatile("tcgen05.commit.cta_group::1.mbarrier::arrive::one.shared::cluster.b64 [%0];" :: "r"(mb) : "memory")
#define TC_WAIT_LD()      asm volatile("tcgen05.wait::ld.sync.aligned;" ::: "memory")
#define TC_WAIT_ST()      asm volatile("tcgen05.wait::st.sync.aligned;" ::: "memory")
#define TC_FENCE_BEFORE() asm volatile("tcgen05.fence::before_thread_sync;" ::: "memory")
#define TC_FENCE_AFTER()  asm volatile("tcgen05.fence::after_thread_sync;" ::: "memory")
#define MB_INIT(mb, n)    asm volatile("mbarrier.init.shared.b64 [%0], %1;" :: "r"(mb), "r"(n) : "memory")
#define FENCE_ASYNC()     asm volatile("fence.proxy.async.shared::cta;" ::: "memory")

__device__ __forceinline__ void mbar_wait0(uint32_t mb) {
    asm volatile(
        "{\n\t.reg .pred P1;\n\t"
        "WL_%=:\n\t"
        "mbarrier.try_wait.parity.acquire.cta.shared::cta.b64 P1, [%0], 0, 0x989680;\n\t"
        "@P1 bra.uni WD_%=;\n\t"
        "bra.uni WL_%=;\n\t"
        "WD_%=:\n\t}"
        :: "r"(mb) : "memory");
}
// TS-mode MMA: A in TMEM ([%1]), B via smem descriptor
__device__ __forceinline__ void mma_f16_ts(uint32_t d, uint32_t a_tmem, uint64_t b, uint32_t idesc, uint32_t acc) {
    asm volatile(
        "{\n\t.reg .pred p;\n\tsetp.ne.u32 p, %5, 0;\n\t"
        "tcgen05.mma.cta_group::1.kind::f16 [%0], [%1], %2, %3, {%4, %4, %4, %4}, p;\n\t}"
        :: "r"(d), "r"(a_tmem), "l"(b), "r"(idesc), "r"(0u), "r"(acc) : "memory");
}
#define LDTM_X32(r, ta) \
    asm volatile("tcgen05.ld.sync.aligned.32x32b.x32.b32 " \
        "{%0,%1,%2,%3,%4,%5,%6,%7,%8,%9,%10,%11,%12,%13,%14,%15," \
        "%16,%17,%18,%19,%20,%21,%22,%23,%24,%25,%26,%27,%28,%29,%30,%31}, [%32];" \
        : "=r"((r)[0]),"=r"((r)[1]),"=r"((r)[2]),"=r"((r)[3]),"=r"((r)[4]),"=r"((r)[5]),"=r"((r)[6]),"=r"((r)[7]), \
          "=r"((r)[8]),"=r"((r)[9]),"=r"((r)[10]),"=r"((r)[11]),"=r"((r)[12]),"=r"((r)[13]),"=r"((r)[14]),"=r"((r)[15]), \
          "=r"((r)[16]),"=r"((r)[17]),"=r"((r)[18]),"=r"((r)[19]),"=r"((r)[20]),"=r"((r)[21]),"=r"((r)[22]),"=r"((r)[23]), \
          "=r"((r)[24]),"=r"((r)[25]),"=r"((r)[26]),"=r"((r)[27]),"=r"((r)[28]),"=r"((r)[29]),"=r"((r)[30]),"=r"((r)[31]) \
        : "r"(ta))
#define STTM_X64(ta, r) \
    asm volatile("tcgen05.st.sync.aligned.32x32b.x64.b32 [%0], " \
        "{%1,%2,%3,%4,%5,%6,%7,%8,%9,%10,%11,%12,%13,%14,%15,%16," \
        "%17,%18,%19,%20,%21,%22,%23,%24,%25,%26,%27,%28,%29,%30,%31,%32," \
        "%33,%34,%35,%36,%37,%38,%39,%40,%41,%42,%43,%44,%45,%46,%47,%48," \
        "%49,%50,%51,%52,%53,%54,%55,%56,%57,%58,%59,%60,%61,%62,%63,%64};" \
        :: "r"(ta), \
           "r"((r)[0]),"r"((r)[1]),"r"((r)[2]),"r"((r)[3]),"r"((r)[4]),"r"((r)[5]),"r"((r)[6]),"r"((r)[7]), \
           "r"((r)[8]),"r"((r)[9]),"r"((r)[10]),"r"((r)[11]),"r"((r)[12]),"r"((r)[13]),"r"((r)[14]),"r"((r)[15]), \
           "r"((r)[16]),"r"((r)[17]),"r"((r)[18]),"r"((r)[19]),"r"((r)[20]),"r"((r)[21]),"r"((r)[22]),"r"((r)[23]), \
           "r"((r)[24]),"r"((r)[25]),"r"((r)[26]),"r"((r)[27]),"r"((r)[28]),"r"((r)[29]),"r"((r)[30]),"r"((r)[31]), \
           "r"((r)[32]),"r"((r)[33]),"r"((r)[34]),"r"((r)[35]),"r"((r)[36]),"r"((r)[37]),"r"((r)[38]),"r"((r)[39]), \
           "r"((r)[40]),"r"((r)[41]),"r"((r)[42]),"r"((r)[43]),"r"((r)[44]),"r"((r)[45]),"r"((r)[46]),"r"((r)[47]), \
           "r"((r)[48]),"r"((r)[49]),"r"((r)[50]),"r"((r)[51]),"r"((r)[52]),"r"((r)[53]),"r"((r)[54]),"r"((r)[55]), \
           "r"((r)[56]),"r"((r)[57]),"r"((r)[58]),"r"((r)[59]),"r"((r)[60]),"r"((r)[61]),"r"((r)[62]),"r"((r)[63]) \
        : "memory")

// SW128 K-major descriptor base: layout=SW128, version=1(Blackwell), SBO=64, LBO=1
static constexpr uint64_t DESC_BASE =
    (uint64_t(2) << 61) | (uint64_t(1) << 46) | (uint64_t(64) << 32) | (uint64_t(1) << 16);
__device__ __forceinline__ uint64_t make_desc(uint32_t addr) {
    return DESC_BASE | ((uint64_t)(addr >> 4) & 0x3FFF);
}

// B tile loader: global bf16 -> blocked SW128 atom layout, 128 threads
// atom = 8 rows x 64 bf16 (1024B); atom_offset = atom_row + atom_col*16
// dst MUST be 1024B-aligned (absolute-address swizzle).
__device__ __forceinline__ void load_tile128(const __nv_bfloat16* __restrict__ src,
                                             char* dst, int nodeBase, int t) {
#pragma unroll
    for (int it = 0; it < 16; it++) {
        int ch = t + 128 * it;              // 2048 chunks of 16B
        int r = ch >> 4, q = ch & 15;
        uint4 v = *(const uint4*)(src + (size_t)(nodeBase + r) * EMBED_DIM + q * 8);
        int bo = ((r >> 3) + ((q >> 3) << 4)) * 1024 + (r & 7) * 128 + (q & 7) * 16;
        *(uint4*)(dst + (bo ^ ((bo >> 3) & 0x70))) = v;
    }
}
#else
// ================= packed f32x2 helpers (fallback path) =================
__device__ __forceinline__ void upk2f(float& x, float& y, ull v) {
    asm("mov.b64 {%0, %1}, %2;" : "=f"(x), "=f"(y) : "l"(v));
}
__device__ __forceinline__ ull pk2f(float x, float y) {
    ull r;
    asm("mov.b64 %0, {%1, %2};" : "=l"(r) : "f"(x), "f"(y));
    return r;
}
__device__ __forceinline__ void fma2f(ull& c, ull a, ull b) {
    asm("fma.rn.f32x2 %0, %1, %2, %3;" : "=l"(c) : "l"(a), "l"(b), "l"(c));
}
#endif

// ---------------- kernel 2: fused Gram / d2 / min-neg / positives ----------
__global__ __launch_bounds__(256, 2) void gemm_kernel(const float* __restrict__ emb) {
    __shared__ int      s_cr[128], s_cc[128];
    __shared__ float    s_qr[128], s_qc[128];
    __shared__ unsigned s_cmin[128];
    __shared__ unsigned s_cnt, s_base;

    const int tid = threadIdx.x;

    // triangular block decode (row-major over upper triangle)
    int by = 0, rem = blockIdx.x;
    while (rem >= NB - by) { rem -= NB - by; by++; }
    const int bx = by + rem;
    const int rowBase = by * 128;
    const int colBase = bx * 128;
    const bool diag = (bx == by);

#if HAS_TCGEN05
    extern __shared__ char smraw[];
    // SW128 swizzle depends on absolute address bits — 1024B-align the tiles.
    char* sm = (char*)(((uintptr_t)smraw + 1023) & ~(uintptr_t)1023);
    char* Bhi = sm;
    char* Blo = sm + TILE_B;

    __shared__ unsigned s_rmin[128];
    __shared__ uint32_t s_tmem;
    __shared__ ull      s_mbar;

    const int w    = tid >> 5;
    const int lane = tid & 31;
    const uint32_t mbar_addr = smem_u32(&s_mbar);
    const uint32_t tptr_addr = smem_u32(&s_tmem);

    if (w == 0) TC_ALLOC(tptr_addr, TMEM_COLS);
    if (tid == 0) { MB_INIT(mbar_addr, 1); s_cnt = 0u; }

    if (tid < 128) {
        s_cr[tid]   = g_comm[rowBase + tid];
        s_qr[tid]   = g_sqn[rowBase + tid];
        s_rmin[tid] = INF_BITS;
    } else {
        int t = tid - 128;
        s_cc[t]   = g_comm[colBase + t];
        s_qc[t]   = g_sqn[colBase + t];
        s_cmin[t] = INF_BITS;
    }
    __syncthreads();                 // s_tmem visible to all
    const uint32_t tmem = s_tmem;

    if (tid < 128) {
        // ---- A rows -> TMEM (hi at cols 0..63, lo at 64..127) ----
        const uint32_t warp_off = (uint32_t)(tid >> 5) << 21;
        uint32_t a[64];
        const uint4* srch = (const uint4*)(g_hi + (size_t)(rowBase + tid) * EMBED_DIM);
#pragma unroll
        for (int q = 0; q < 16; q++) {
            uint4 v = srch[q];
            a[4*q] = v.x; a[4*q+1] = v.y; a[4*q+2] = v.z; a[4*q+3] = v.w;
        }
        STTM_X64(tmem + TMEM_A_HI + warp_off, a);
        const uint4* srcl = (const uint4*)(g_lo + (size_t)(rowBase + tid) * EMBED_DIM);
#pragma unroll
        for (int q = 0; q < 16; q++) {
            uint4 v = srcl[q];
            a[4*q] = v.x; a[4*q+1] = v.y; a[4*q+2] = v.z; a[4*q+3] = v.w;
        }
        STTM_X64(tmem + TMEM_A_LO + warp_off, a);
        TC_WAIT_ST();
    } else {
        // ---- B tiles -> smem (blocked SW128 atoms) ----
        load_tile128(g_hi, Bhi, colBase, tid - 128);
        load_tile128(g_lo, Blo, colBase, tid - 128);
    }
    TC_FENCE_BEFORE();
    FENCE_ASYNC();
    __syncthreads();
    if (w == 0) TC_RELINQ();

    if (w == 0 && elect_one()) {
        TC_FENCE_AFTER();
        uint64_t bhid = make_desc(smem_u32(Bhi));
        uint64_t blod = make_desc(smem_u32(Blo));
        // terms: Ahi*Bhi + Ahi*Blo + Alo*Bhi  (lo*lo dropped, ~4e-5 abs on dot)
        uint32_t aoff[3] = { TMEM_A_HI, TMEM_A_HI, TMEM_A_LO };
        uint64_t bdsc[3] = { bhid, blod, bhid };
        uint32_t acc = 0;
#pragma unroll
        for (int t = 0; t < 3; t++) {
#pragma unroll
            for (int ks = 0; ks < 8; ks++) {
                uint64_t ko = (ks < 4) ? (uint64_t)(2 * ks) : (uint64_t)(1024 + 2 * (ks - 4));
                mma_f16_ts(tmem + TMEM_D, tmem + aoff[t] + ks * 8, bdsc[t] + ko, MMA_IDESC, acc);
                acc = 1;
            }
        }
        TC_COMMIT(mbar_addr);
    }

    mbar_wait0(mbar_addr);
    TC_FENCE_AFTER();

    // epilogue: warp w -> rows (w&3)*32.., cols (w>>2)*64..
    const int rl    = (w & 3) * 32 + lane;
    const int cbase = (w >> 2) * 64;
    const uint32_t warp_off = (uint32_t)(w & 3) << 21;

    uint32_t du[64];
    LDTM_X32(du,      tmem + TMEM_D + warp_off + cbase);
    LDTM_X32(du + 32, tmem + TMEM_D + warp_off + cbase + 32);
    TC_WAIT_LD();

    const float sqr = s_qr[rl];
    const int   cr  = s_cr[rl];
    float rmin2 = CUDART_INF_F;
    ull nmask = 0ull, pmask = 0ull;
#pragma unroll
    for (int j = 0; j < 64; j++) {
        const int ci = cbase + j;
        float d2 = fmaxf(sqr + s_qc[ci] - 2.0f * __uint_as_float(du[j]), 0.0f);
        du[j] = __float_as_uint(d2);
        if (cr != s_cc[ci]) {
            nmask |= 1ull << j;
            rmin2 = fminf(rmin2, d2);
        } else if (!diag || rl != ci) {
            pmask |= 1ull << j;
        }
    }
    if (rmin2 < CUDART_INF_F) atomicMin(&s_rmin[rl], __float_as_uint(rmin2));

    if (!diag) {
        // column-min across the warp's 32 rows: one redux per column
#pragma unroll
        for (int j = 0; j < 64; j++) {
            unsigned v = ((nmask >> j) & 1) ? du[j] : INF_BITS;
            v = __reduce_min_sync(0xffffffffu, v);
            if (lane == 0 && v < INF_BITS)
                atomicMin(&s_cmin[cbase + j], v);
        }
    }

    int h = __popcll(pmask);
    if (!diag) h *= 2;
    unsigned lbase = 0u;
    if (h) lbase = atomicAdd(&s_cnt, (unsigned)h);
    __syncthreads();

    if (tid == 0) s_base = s_cnt ? atomicAdd(&g_paircnt, s_cnt) : 0u;
    if (tid < 128 && s_rmin[tid] != INF_BITS)
        atomicMin(&g_minneg[rowBase + tid], s_rmin[tid]);
    if (!diag && tid >= 128 && s_cmin[tid - 128] != INF_BITS)
        atomicMin(&g_minneg[colBase + tid - 128], s_cmin[tid - 128]);
    __syncthreads();

    if (h) {
        unsigned p = s_base + lbase;
        ull m = pmask;
        while (m) {
            int j = __ffsll((long long)m) - 1;
            m &= m - 1;
            unsigned db = du[j];
            if (p < PAIR_CAP) g_pair[p] = ((ull)(unsigned)(rowBase + rl) << 32) | db;
            p++;
            if (!diag) {
                if (p < PAIR_CAP) g_pair[p] = ((ull)(unsigned)(colBase + cbase + j) << 32) | db;
                p++;
            }
        }
    }

    __syncthreads();
    if (w == 0) TC_DEALLOC(tmem, TMEM_COLS);

#else  // ---------------- FFMA2 fallback body (compile-only on plain PTX) ----
    extern __shared__ float smf[];
    float* As = smf;
    float* Bs = smf + 128 * 128;

    if (tid < 128) {
        s_cr[tid] = g_comm[rowBase + tid];
        s_qr[tid] = g_sqn[rowBase + tid];
        s_cmin[tid] = INF_BITS;
    } else {
        int t = tid - 128;
        s_cc[t] = g_comm[colBase + t];
        s_qc[t] = g_sqn[colBase + t];
    }
    if (tid == 0) s_cnt = 0u;

    {
        int r = tid & 127;
        const float4* src = (const float4*)(emb + (size_t)((tid < 128 ? rowBase : colBase) + r) * EMBED_DIM);
        float* dst = (tid < 128) ? As : Bs;
#pragma unroll
        for (int q = 0; q < 32; q++) {
            float4 v = src[q];
            int k = q * 4;
            dst[(k + 0) * 128 + r] = v.x; dst[(k + 1) * 128 + r] = v.y;
            dst[(k + 2) * 128 + r] = v.z; dst[(k + 3) * 128 + r] = v.w;
        }
    }
    __syncthreads();

    const int tx = tid & 15;
    const int ty = tid >> 4;

    ull acc[8][4];
#pragma unroll
    for (int r = 0; r < 8; r++)
#pragma unroll
        for (int c = 0; c < 4; c++) acc[r][c] = 0ull;

#pragma unroll 4
    for (int k = 0; k < 128; k++) {
        const float* ap = As + k * 128 + ty * 8;
        const float* bp = Bs + k * 128;
        ull b0 = *(const ull*)(bp + 2 * tx);
        ull b1 = *(const ull*)(bp + 2 * tx + 32);
        ull b2 = *(const ull*)(bp + 2 * tx + 64);
        ull b3 = *(const ull*)(bp + 2 * tx + 96);
        float4 a0 = *(const float4*)ap;
        float4 a1 = *(const float4*)(ap + 4);
        float ar[8] = {a0.x, a0.y, a0.z, a0.w, a1.x, a1.y, a1.z, a1.w};
#pragma unroll
        for (int rr = 0; rr < 8; rr++) {
            ull a2 = pk2f(ar[rr], ar[rr]);
            fma2f(acc[rr][0], a2, b0);
            fma2f(acc[rr][1], a2, b1);
            fma2f(acc[rr][2], a2, b2);
            fma2f(acc[rr][3], a2, b3);
        }
    }

    float dist[8][8];
    float cmin[8];
#pragma unroll
    for (int cc = 0; cc < 8; cc++) cmin[cc] = CUDART_INF_F;
    int h = 0;
#pragma unroll
    for (int rr = 0; rr < 8; rr++) {
        const int ri  = ty * 8 + rr;
        const float sqr = s_qr[ri];
        const int   cr  = s_cr[ri];
        float rmin = CUDART_INF_F;
#pragma unroll
        for (int cc = 0; cc < 8; cc++) {
            const int ci = 2 * (tx + 16 * (cc >> 1)) + (cc & 1);
            float lo, hi;
            upk2f(lo, hi, acc[rr][cc >> 1]);
            float dot = (cc & 1) ? hi : lo;
            float d2 = fmaxf(sqr + s_qc[ci] - 2.0f * dot, 0.0f);
            dist[rr][cc] = d2;
            if (cr != s_cc[ci]) {
                rmin = fminf(rmin, d2);
                cmin[cc] = fminf(cmin[cc], d2);
            } else if (!diag || ri != ci) {
                h += diag ? 1 : 2;
            }
        }
        rmin = fminf(rmin, __shfl_xor_sync(0xffffffffu, rmin, 1));
        rmin = fminf(rmin, __shfl_xor_sync(0xffffffffu, rmin, 2));
        rmin = fminf(rmin, __shfl_xor_sync(0xffffffffu, rmin, 4));
        rmin = fminf(rmin, __shfl_xor_sync(0xffffffffu, rmin, 8));
        if (tx == 0 && rmin < CUDART_INF_F)
            atomicMin(&g_minneg[rowBase + ri], __float_as_uint(rmin));
    }

    if (!diag) {
#pragma unroll
        for (int cc = 0; cc < 8; cc++) {
            if (cmin[cc] < CUDART_INF_F) {
                const int ci = 2 * (tx + 16 * (cc >> 1)) + (cc & 1);
                atomicMin(&s_cmin[ci], __float_as_uint(cmin[cc]));
            }
        }
    }

    unsigned lbase = 0u;
    if (h) lbase = atomicAdd(&s_cnt, (unsigned)h);
    __syncthreads();
    if (tid == 0) s_base = s_cnt ? atomicAdd(&g_paircnt, s_cnt) : 0u;
    if (!diag && tid < 128 && s_cmin[tid] != INF_BITS)
        atomicMin(&g_minneg[colBase + tid], s_cmin[tid]);
    __syncthreads();

    if (h) {
        unsigned p = s_base + lbase;
#pragma unroll
        for (int rr = 0; rr < 8; rr++) {
            const int ri = ty * 8 + rr;
            const int cr = s_cr[ri];
#pragma unroll
            for (int cc = 0; cc < 8; cc++) {
                const int ci = 2 * (tx + 16 * (cc >> 1)) + (cc & 1);
                if (cr == s_cc[ci] && (!diag || ri != ci)) {
                    unsigned db = __float_as_uint(dist[rr][cc]);
                    if (p < PAIR_CAP)
                        g_pair[p] = ((ull)(unsigned)(rowBase + ri) << 32) | db;
                    p++;
                    if (!diag) {
                        if (p < PAIR_CAP)
                            g_pair[p] = ((ull)(unsigned)(colBase + ci) << 32) | db;
                        p++;
                    }
                }
            }
        }
    }
#endif
}

// ---------------- kernel 3: hinge over positive pairs (d2 -> d) ------------
__global__ void pair_kernel() {
    unsigned n = g_paircnt;
    if (n > PAIR_CAP) n = PAIR_CAP;
    const int tid = threadIdx.x;
    double t = 0.0;
    ull c = 0ull;
    for (unsigned i = blockIdx.x * blockDim.x + tid; i < n; i += gridDim.x * blockDim.x) {
        ull pk = g_pair[i];
        int r = (int)(pk >> 32);
        unsigned mb = g_minneg[r];
        if (mb < INF_BITS) {  // has_neg
            float d  = sqrtf(__uint_as_float((unsigned)pk));
            float mn = sqrtf(__uint_as_float(mb));
            float tl = d - mn + MARGIN;
            if (tl > 0.0f) t += (double)tl;
            c++;
        }
    }
    __shared__ double st[256];
    __shared__ ull    sc[256];
    st[tid] = t; sc[tid] = c;
    __syncthreads();
    for (int s = 128; s; s >>= 1) {
        if (tid < s) { st[tid] += st[tid + s]; sc[tid] += sc[tid + s]; }
        __syncthreads();
    }
    if (tid == 0) {
        if (st[0] != 0.0) atomicAdd(&g_total, st[0]);
        if (sc[0])        atomicAdd(&g_valid, sc[0]);
    }
}

// ---------------- kernel 4: finalize ----------------
__global__ void final_kernel(float* __restrict__ out) {
    out[0] = g_valid ? (float)(g_total / (double)g_valid) : 0.0f;
}

// ---------------- launch ----------------
extern "C" void kernel_launch(void* const* d_in, const int* in_sizes, int n_in,
                              void* d_out, int out_size) {
    const float* emb  = (const float*)d_in[0];
    const int*   comm = (const int*)d_in[1];
    float*       out  = (float*)d_out;

    init_kernel<<<1, 256>>>(comm);
    sqn_kernel<<<N_NODES / 8, 256>>>(emb);
    split_kernel<<<(N_NODES * EMBED_DIM / 4) / 256, 256>>>(emb);

    cudaFuncSetAttribute(gemm_kernel, cudaFuncAttributeMaxDynamicSharedMemorySize, SMEM_BYTES);
    gemm_kernel<<<NBLOCKS, 256, SMEM_BYTES>>>(emb);

    pair_kernel<<<512, 256>>>();
    final_kernel<<<1, 1>>>(out);
}

// round 13
// speedup vs baseline: 3.8602x; 1.5390x over previous
#include <cuda_runtime.h>
#include <cuda_bf16.h>
#include <math_constants.h>
#include <cstdint>

typedef unsigned long long ull;

#define N_NODES   8192
#define EMBED_DIM 128
#define MARGIN    1.0f
#define NB        (N_NODES / 128)
#define NBLOCKS   (NB * (NB + 1) / 2)      // 2080 upper-triangle tiles
#define PAIR_CAP  (1u << 21)
#define TILE_B    (128 * 128 * 2)          // one 128x128 bf16 tile = 32KB
#define SMEM_BYTES (2 * TILE_B + 1024)     // B_hi + B_lo + alignment slack

#define MMA_IDESC 0x8200490u               // kind::f16: F32 acc, bf16 a/b, M=128, N=128
#define INF_BITS  0x7f800000u
#define TMEM_A_HI 0
#define TMEM_A_LO 64
#define TMEM_D    128
#define TMEM_COLS 256

#if defined(__CUDA_ARCH__) && (defined(__CUDA_ARCH_FEAT_SM103_ALL) || defined(__CUDA_ARCH_FEAT_SM100_ALL) || defined(__CUDA_ARCH_FEAT_SM101_ALL))
#define HAS_TCGEN05 1
#else
#define HAS_TCGEN05 0
#endif

// ---------------- device scratch ----------------
__device__ int            g_comm[N_NODES];
__device__ float          g_sqn[N_NODES];
__device__ unsigned       g_minneg[N_NODES];     // bits of min negative d^2
__device__ unsigned       g_paircnt;
__device__ ull            g_pair[PAIR_CAP];      // hi32=anchor row, lo32=d^2 bits
__device__ double         g_total;
__device__ ull            g_valid;
__device__ __nv_bfloat16  g_hi[N_NODES * EMBED_DIM];
__device__ __nv_bfloat16  g_lo[N_NODES * EMBED_DIM];

// ---------------- kernel 0: dtype probe + convert + init ----------------
__global__ void init_kernel(const int* __restrict__ comm_raw) {
    __shared__ int s_or;
    int tid = threadIdx.x;
    if (tid == 0) s_or = 0;
    __syncthreads();
    int acc = 0;
    for (int i = tid; i < N_NODES / 2; i += blockDim.x)
        acc |= comm_raw[2 * i + 1];
    if (acc) atomicOr(&s_or, 1);
    __syncthreads();
    bool is64 = (s_or == 0);
    const long long* c64 = (const long long*)comm_raw;
    for (int i = tid; i < N_NODES; i += blockDim.x) {
        g_comm[i]   = is64 ? (int)c64[i] : comm_raw[i];
        g_minneg[i] = INF_BITS;
    }
    if (tid == 0) { g_paircnt = 0u; g_total = 0.0; g_valid = 0ull; }
}

// ---------------- kernel 1: squared norms ----------------
__global__ void sqn_kernel(const float* __restrict__ emb) {
    int warp = threadIdx.x >> 5, lane = threadIdx.x & 31;
    int row = blockIdx.x * 8 + warp;
    if (row >= N_NODES) return;
    const float* p = emb + (size_t)row * EMBED_DIM;
    float s = 0.f;
#pragma unroll
    for (int k = lane; k < EMBED_DIM; k += 32) { float v = p[k]; s = fmaf(v, v, s); }
#pragma unroll
    for (int o = 16; o; o >>= 1) s += __shfl_xor_sync(0xffffffffu, s, o);
    if (lane == 0) g_sqn[row] = s;
}

// ---------------- kernel 1b: bf16 hi/lo split ----------------
__global__ void split_kernel(const float* __restrict__ emb) {
    int i = blockIdx.x * blockDim.x + threadIdx.x;   // one float4 per thread
    float4 v = ((const float4*)emb)[i];
    __nv_bfloat16 h0 = __float2bfloat16(v.x), h1 = __float2bfloat16(v.y);
    __nv_bfloat16 h2 = __float2bfloat16(v.z), h3 = __float2bfloat16(v.w);
    __nv_bfloat16 l0 = __float2bfloat16(v.x - __bfloat162float(h0));
    __nv_bfloat16 l1 = __float2bfloat16(v.y - __bfloat162float(h1));
    __nv_bfloat16 l2 = __float2bfloat16(v.z - __bfloat162float(h2));
    __nv_bfloat16 l3 = __float2bfloat16(v.w - __bfloat162float(h3));
    ((__nv_bfloat162*)g_hi)[2 * i]     = __nv_bfloat162(h0, h1);
    ((__nv_bfloat162*)g_hi)[2 * i + 1] = __nv_bfloat162(h2, h3);
    ((__nv_bfloat162*)g_lo)[2 * i]     = __nv_bfloat162(l0, l1);
    ((__nv_bfloat162*)g_lo)[2 * i + 1] = __nv_bfloat162(l2, l3);
}

#if HAS_TCGEN05
// ================= tcgen05 helpers (sm_103a targets only) =================
__device__ __forceinline__ uint32_t smem_u32(const void* p) {
    uint32_t a;
    asm("{ .reg .u64 t; cvta.to.shared.u64 t, %1; cvt.u32.u64 %0, t; }" : "=r"(a) : "l"(p));
    return a;
}
__device__ __forceinline__ uint32_t elect_one() {
    uint32_t p;
    asm volatile("{ .reg .pred p; elect.sync _|p, 0xFFFFFFFF; selp.b32 %0, 1, 0, p; }" : "=r"(p));
    return p;
}
#define TC_ALLOC(sm, n)   asm volatile("tcgen05.alloc.cta_group::1.sync.aligned.shared::cta.b32 [%0], %1;" :: "r"(sm), "r"(n) : "memory")
#define TC_DEALLOC(t, n)  asm volatile("tcgen05.dealloc.cta_group::1.sync.aligned.b32 %0, %1;" :: "r"(t), "r"(n))
#define TC_RELINQ()       asm volatile("tcgen05.relinquish_alloc_permit.cta_group::1.sync.aligned;")
#define TC_COMMIT(mb)     asm volatile("tcgen05.commit.cta_group::1.mbarrier::arrive::one.shared::cluster.b64 [%0];" :: "r"(mb) : "memory")
#define TC_WAIT_LD()      asm volatile("tcgen05.wait::ld.sync.aligned;" ::: "memory")
#define TC_WAIT_ST()      asm volatile("tcgen05.wait::st.sync.aligned;" ::: "memory")
#define TC_FENCE_BEFORE() asm volatile("tcgen05.fence::before_thread_sync;" ::: "memory")
#define TC_FENCE_AFTER()  asm volatile("tcgen05.fence::after_thread_sync;" ::: "memory")
#define MB_INIT(mb, n)    asm volatile("mbarrier.init.shared.b64 [%0], %1;" :: "r"(mb), "r"(n) : "memory")
#define FENCE_ASYNC()     asm volatile("fence.proxy.async.shared::cta;" ::: "memory")

__device__ __forceinline__ void mbar_wait0(uint32_t mb) {
    asm volatile(
        "{\n\t.reg .pred P1;\n\t"
        "WL_%=:\n\t"
        "mbarrier.try_wait.parity.acquire.cta.shared::cta.b64 P1, [%0], 0, 0x989680;\n\t"
        "@P1 bra.uni WD_%=;\n\t"
        "bra.uni WL_%=;\n\t"
        "WD_%=:\n\t}"
        :: "r"(mb) : "memory");
}
// TS-mode MMA: A in TMEM ([%1]), B via smem descriptor
__device__ __forceinline__ void mma_f16_ts(uint32_t d, uint32_t a_tmem, uint64_t b, uint32_t idesc, uint32_t acc) {
    asm volatile(
        "{\n\t.reg .pred p;\n\tsetp.ne.u32 p, %5, 0;\n\t"
        "tcgen05.mma.cta_group::1.kind::f16 [%0], [%1], %2, %3, {%4, %4, %4, %4}, p;\n\t}"
        :: "r"(d), "r"(a_tmem), "l"(b), "r"(idesc), "r"(0u), "r"(acc) : "memory");
}
#define LDTM_X32(r, ta) \
    asm volatile("tcgen05.ld.sync.aligned.32x32b.x32.b32 " \
        "{%0,%1,%2,%3,%4,%5,%6,%7,%8,%9,%10,%11,%12,%13,%14,%15," \
        "%16,%17,%18,%19,%20,%21,%22,%23,%24,%25,%26,%27,%28,%29,%30,%31}, [%32];" \
        : "=r"((r)[0]),"=r"((r)[1]),"=r"((r)[2]),"=r"((r)[3]),"=r"((r)[4]),"=r"((r)[5]),"=r"((r)[6]),"=r"((r)[7]), \
          "=r"((r)[8]),"=r"((r)[9]),"=r"((r)[10]),"=r"((r)[11]),"=r"((r)[12]),"=r"((r)[13]),"=r"((r)[14]),"=r"((r)[15]), \
          "=r"((r)[16]),"=r"((r)[17]),"=r"((r)[18]),"=r"((r)[19]),"=r"((r)[20]),"=r"((r)[21]),"=r"((r)[22]),"=r"((r)[23]), \
          "=r"((r)[24]),"=r"((r)[25]),"=r"((r)[26]),"=r"((r)[27]),"=r"((r)[28]),"=r"((r)[29]),"=r"((r)[30]),"=r"((r)[31]) \
        : "r"(ta))
#define STTM_X64(ta, r) \
    asm volatile("tcgen05.st.sync.aligned.32x32b.x64.b32 [%0], " \
        "{%1,%2,%3,%4,%5,%6,%7,%8,%9,%10,%11,%12,%13,%14,%15,%16," \
        "%17,%18,%19,%20,%21,%22,%23,%24,%25,%26,%27,%28,%29,%30,%31,%32," \
        "%33,%34,%35,%36,%37,%38,%39,%40,%41,%42,%43,%44,%45,%46,%47,%48," \
        "%49,%50,%51,%52,%53,%54,%55,%56,%57,%58,%59,%60,%61,%62,%63,%64};" \
        :: "r"(ta), \
           "r"((r)[0]),"r"((r)[1]),"r"((r)[2]),"r"((r)[3]),"r"((r)[4]),"r"((r)[5]),"r"((r)[6]),"r"((r)[7]), \
           "r"((r)[8]),"r"((r)[9]),"r"((r)[10]),"r"((r)[11]),"r"((r)[12]),"r"((r)[13]),"r"((r)[14]),"r"((r)[15]), \
           "r"((r)[16]),"r"((r)[17]),"r"((r)[18]),"r"((r)[19]),"r"((r)[20]),"r"((r)[21]),"r"((r)[22]),"r"((r)[23]), \
           "r"((r)[24]),"r"((r)[25]),"r"((r)[26]),"r"((r)[27]),"r"((r)[28]),"r"((r)[29]),"r"((r)[30]),"r"((r)[31]), \
           "r"((r)[32]),"r"((r)[33]),"r"((r)[34]),"r"((r)[35]),"r"((r)[36]),"r"((r)[37]),"r"((r)[38]),"r"((r)[39]), \
           "r"((r)[40]),"r"((r)[41]),"r"((r)[42]),"r"((r)[43]),"r"((r)[44]),"r"((r)[45]),"r"((r)[46]),"r"((r)[47]), \
           "r"((r)[48]),"r"((r)[49]),"r"((r)[50]),"r"((r)[51]),"r"((r)[52]),"r"((r)[53]),"r"((r)[54]),"r"((r)[55]), \
           "r"((r)[56]),"r"((r)[57]),"r"((r)[58]),"r"((r)[59]),"r"((r)[60]),"r"((r)[61]),"r"((r)[62]),"r"((r)[63]) \
        : "memory")

// SW128 K-major descriptor base: layout=SW128, version=1(Blackwell), SBO=64, LBO=1
static constexpr uint64_t DESC_BASE =
    (uint64_t(2) << 61) | (uint64_t(1) << 46) | (uint64_t(64) << 32) | (uint64_t(1) << 16);
__device__ __forceinline__ uint64_t make_desc(uint32_t addr) {
    return DESC_BASE | ((uint64_t)(addr >> 4) & 0x3FFF);
}

// B tile loader: global bf16 -> blocked SW128 atom layout, 128 threads
// atom = 8 rows x 64 bf16 (1024B); atom_offset = atom_row + atom_col*16
// dst MUST be 1024B-aligned (absolute-address swizzle).
__device__ __forceinline__ void load_tile128(const __nv_bfloat16* __restrict__ src,
                                             char* dst, int nodeBase, int t) {
#pragma unroll
    for (int it = 0; it < 16; it++) {
        int ch = t + 128 * it;              // 2048 chunks of 16B
        int r = ch >> 4, q = ch & 15;
        uint4 v = *(const uint4*)(src + (size_t)(nodeBase + r) * EMBED_DIM + q * 8);
        int bo = ((r >> 3) + ((q >> 3) << 4)) * 1024 + (r & 7) * 128 + (q & 7) * 16;
        *(uint4*)(dst + (bo ^ ((bo >> 3) & 0x70))) = v;
    }
}
#else
// ================= packed f32x2 helpers (fallback path) =================
__device__ __forceinline__ void upk2f(float& x, float& y, ull v) {
    asm("mov.b64 {%0, %1}, %2;" : "=f"(x), "=f"(y) : "l"(v));
}
__device__ __forceinline__ ull pk2f(float x, float y) {
    ull r;
    asm("mov.b64 %0, {%1, %2};" : "=l"(r) : "f"(x), "f"(y));
    return r;
}
__device__ __forceinline__ void fma2f(ull& c, ull a, ull b) {
    asm("fma.rn.f32x2 %0, %1, %2, %3;" : "=l"(c) : "l"(a), "l"(b), "l"(c));
}
#endif

// ---------------- kernel 2: fused Gram / d2 / min-neg / positives ----------
__global__ __launch_bounds__(256, 2) void gemm_kernel(const float* __restrict__ emb) {
    __shared__ int      s_cr[128], s_cc[128];
    __shared__ float    s_qr[128], s_qc[128];
    __shared__ unsigned s_cmin[128];
    __shared__ unsigned s_cnt, s_base;

    const int tid = threadIdx.x;

    // triangular block decode (row-major over upper triangle)
    int by = 0, rem = blockIdx.x;
    while (rem >= NB - by) { rem -= NB - by; by++; }
    const int bx = by + rem;
    const int rowBase = by * 128;
    const int colBase = bx * 128;
    const bool diag = (bx == by);

#if HAS_TCGEN05
    extern __shared__ char smraw[];
    // SW128 swizzle depends on absolute address bits — 1024B-align the tiles.
    char* sm = (char*)(((uintptr_t)smraw + 1023) & ~(uintptr_t)1023);
    char* Bhi = sm;
    char* Blo = sm + TILE_B;

    __shared__ unsigned s_rmin[128];
    __shared__ uint32_t s_tmem;
    __shared__ ull      s_mbar;

    const int w    = tid >> 5;
    const int lane = tid & 31;
    const uint32_t mbar_addr = smem_u32(&s_mbar);
    const uint32_t tptr_addr = smem_u32(&s_tmem);

    if (w == 0) TC_ALLOC(tptr_addr, TMEM_COLS);
    if (tid == 0) MB_INIT(mbar_addr, 1);

    if (tid < 128) {
        s_cr[tid]   = g_comm[rowBase + tid];
        s_qr[tid]   = g_sqn[rowBase + tid];
        s_rmin[tid] = INF_BITS;
    } else {
        int t = tid - 128;
        s_cc[t]   = g_comm[colBase + t];
        s_qc[t]   = g_sqn[colBase + t];
        s_cmin[t] = INF_BITS;
    }
    __syncthreads();                 // s_tmem visible to all
    const uint32_t tmem = s_tmem;

    if (tid < 128) {
        // ---- A rows -> TMEM (hi at cols 0..63, lo at 64..127) ----
        const uint32_t aw_off = (uint32_t)(tid >> 5) << 21;
        uint32_t a[64];
        const uint4* srch = (const uint4*)(g_hi + (size_t)(rowBase + tid) * EMBED_DIM);
#pragma unroll
        for (int q = 0; q < 16; q++) {
            uint4 v = srch[q];
            a[4*q] = v.x; a[4*q+1] = v.y; a[4*q+2] = v.z; a[4*q+3] = v.w;
        }
        STTM_X64(tmem + TMEM_A_HI + aw_off, a);
        const uint4* srcl = (const uint4*)(g_lo + (size_t)(rowBase + tid) * EMBED_DIM);
#pragma unroll
        for (int q = 0; q < 16; q++) {
            uint4 v = srcl[q];
            a[4*q] = v.x; a[4*q+1] = v.y; a[4*q+2] = v.z; a[4*q+3] = v.w;
        }
        STTM_X64(tmem + TMEM_A_LO + aw_off, a);
        TC_WAIT_ST();
    } else {
        // ---- B tiles -> smem (blocked SW128 atoms) ----
        load_tile128(g_hi, Bhi, colBase, tid - 128);
        load_tile128(g_lo, Blo, colBase, tid - 128);
    }
    TC_FENCE_BEFORE();
    FENCE_ASYNC();
    __syncthreads();
    if (w == 0) TC_RELINQ();

    if (w == 0 && elect_one()) {
        TC_FENCE_AFTER();
        uint64_t bhid = make_desc(smem_u32(Bhi));
        uint64_t blod = make_desc(smem_u32(Blo));
        // terms: Ahi*Bhi + Ahi*Blo + Alo*Bhi  (lo*lo dropped, ~4e-5 abs on dot)
        uint32_t aoff[3] = { TMEM_A_HI, TMEM_A_HI, TMEM_A_LO };
        uint64_t bdsc[3] = { bhid, blod, bhid };
        uint32_t acc = 0;
#pragma unroll
        for (int t = 0; t < 3; t++) {
#pragma unroll
            for (int ks = 0; ks < 8; ks++) {
                uint64_t ko = (ks < 4) ? (uint64_t)(2 * ks) : (uint64_t)(1024 + 2 * (ks - 4));
                mma_f16_ts(tmem + TMEM_D, tmem + aoff[t] + ks * 8, bdsc[t] + ko, MMA_IDESC, acc);
                acc = 1;
            }
        }
        TC_COMMIT(mbar_addr);
    }

    mbar_wait0(mbar_addr);
    TC_FENCE_AFTER();

    // ---- epilogue: warp w -> rows (w&3)*32.., cols (w>>2)*64.., two 32-col chunks ----
    // All du[] indices are compile-time constants (no local-memory spill).
    const int rl     = (w & 3) * 32 + lane;
    const int cbase0 = (w >> 2) * 64;
    const uint32_t dw_off = (uint32_t)(w & 3) << 21;

    const float sqr = s_qr[rl];
    const int   cr  = s_cr[rl];
    float rmin2 = CUDART_INF_F;

#pragma unroll
    for (int ch = 0; ch < 2; ch++) {
        const int cb = cbase0 + 32 * ch;
        uint32_t du[32];
        LDTM_X32(du, tmem + TMEM_D + dw_off + cb);
        TC_WAIT_LD();

        unsigned nm = 0u, pm = 0u;
#pragma unroll
        for (int j = 0; j < 32; j++) {
            const int ci = cb + j;
            float d2 = fmaxf(sqr + s_qc[ci] - 2.0f * __uint_as_float(du[j]), 0.0f);
            du[j] = __float_as_uint(d2);
            if (cr != s_cc[ci]) {
                nm |= 1u << j;
                rmin2 = fminf(rmin2, d2);
            } else if (!diag || rl != ci) {
                pm |= 1u << j;
            }
        }

        if (!diag) {
#pragma unroll
            for (int j = 0; j < 32; j++) {
                unsigned v = ((nm >> j) & 1u) ? du[j] : INF_BITS;
                v = __reduce_min_sync(0xffffffffu, v);
                if (lane == 0 && v < INF_BITS)
                    atomicMin(&s_cmin[cb + j], v);
            }
        }

        // ---- pair emission: warp exclusive scan + one global atomic ----
        unsigned h = (unsigned)__popc(pm);
        if (!diag) h *= 2u;
        unsigned incl = h;
#pragma unroll
        for (int d = 1; d < 32; d <<= 1) {
            unsigned t = __shfl_up_sync(0xffffffffu, incl, d);
            if (lane >= d) incl += t;
        }
        unsigned tot = __shfl_sync(0xffffffffu, incl, 31);
        unsigned base = 0u;
        if (tot) {
            if (lane == 31) base = atomicAdd(&g_paircnt, tot);
            base = __shfl_sync(0xffffffffu, base, 31);
        }
        unsigned p = base + incl - h;
#pragma unroll
        for (int j = 0; j < 32; j++) {
            if ((pm >> j) & 1u) {
                unsigned db = du[j];
                if (p < PAIR_CAP) g_pair[p] = ((ull)(unsigned)(rowBase + rl) << 32) | db;
                p++;
                if (!diag) {
                    if (p < PAIR_CAP) g_pair[p] = ((ull)(unsigned)(colBase + cb + j) << 32) | db;
                    p++;
                }
            }
        }
    }

    if (rmin2 < CUDART_INF_F) atomicMin(&s_rmin[rl], __float_as_uint(rmin2));
    __syncthreads();

    if (tid < 128 && s_rmin[tid] != INF_BITS)
        atomicMin(&g_minneg[rowBase + tid], s_rmin[tid]);
    if (!diag && tid >= 128 && s_cmin[tid - 128] != INF_BITS)
        atomicMin(&g_minneg[colBase + tid - 128], s_cmin[tid - 128]);

    __syncthreads();
    if (w == 0) TC_DEALLOC(tmem, TMEM_COLS);

#else  // ---------------- FFMA2 fallback body (compile-only on plain PTX) ----
    extern __shared__ float smf[];
    float* As = smf;
    float* Bs = smf + 128 * 128;

    if (tid < 128) {
        s_cr[tid] = g_comm[rowBase + tid];
        s_qr[tid] = g_sqn[rowBase + tid];
        s_cmin[tid] = INF_BITS;
    } else {
        int t = tid - 128;
        s_cc[t] = g_comm[colBase + t];
        s_qc[t] = g_sqn[colBase + t];
    }
    if (tid == 0) s_cnt = 0u;

    {
        int r = tid & 127;
        const float4* src = (const float4*)(emb + (size_t)((tid < 128 ? rowBase : colBase) + r) * EMBED_DIM);
        float* dst = (tid < 128) ? As : Bs;
#pragma unroll
        for (int q = 0; q < 32; q++) {
            float4 v = src[q];
            int k = q * 4;
            dst[(k + 0) * 128 + r] = v.x; dst[(k + 1) * 128 + r] = v.y;
            dst[(k + 2) * 128 + r] = v.z; dst[(k + 3) * 128 + r] = v.w;
        }
    }
    __syncthreads();

    const int tx = tid & 15;
    const int ty = tid >> 4;

    ull acc[8][4];
#pragma unroll
    for (int r = 0; r < 8; r++)
#pragma unroll
        for (int c = 0; c < 4; c++) acc[r][c] = 0ull;

#pragma unroll 4
    for (int k = 0; k < 128; k++) {
        const float* ap = As + k * 128 + ty * 8;
        const float* bp = Bs + k * 128;
        ull b0 = *(const ull*)(bp + 2 * tx);
        ull b1 = *(const ull*)(bp + 2 * tx + 32);
        ull b2 = *(const ull*)(bp + 2 * tx + 64);
        ull b3 = *(const ull*)(bp + 2 * tx + 96);
        float4 a0 = *(const float4*)ap;
        float4 a1 = *(const float4*)(ap + 4);
        float ar[8] = {a0.x, a0.y, a0.z, a0.w, a1.x, a1.y, a1.z, a1.w};
#pragma unroll
        for (int rr = 0; rr < 8; rr++) {
            ull a2 = pk2f(ar[rr], ar[rr]);
            fma2f(acc[rr][0], a2, b0);
            fma2f(acc[rr][1], a2, b1);
            fma2f(acc[rr][2], a2, b2);
            fma2f(acc[rr][3], a2, b3);
        }
    }

    float dist[8][8];
    float cmin[8];
#pragma unroll
    for (int cc = 0; cc < 8; cc++) cmin[cc] = CUDART_INF_F;
    int h = 0;
#pragma unroll
    for (int rr = 0; rr < 8; rr++) {
        const int ri  = ty * 8 + rr;
        const float sqr = s_qr[ri];
        const int   cr  = s_cr[ri];
        float rmin = CUDART_INF_F;
#pragma unroll
        for (int cc = 0; cc < 8; cc++) {
            const int ci = 2 * (tx + 16 * (cc >> 1)) + (cc & 1);
            float lo, hi;
            upk2f(lo, hi, acc[rr][cc >> 1]);
            float dot = (cc & 1) ? hi : lo;
            float d2 = fmaxf(sqr + s_qc[ci] - 2.0f * dot, 0.0f);
            dist[rr][cc] = d2;
            if (cr != s_cc[ci]) {
                rmin = fminf(rmin, d2);
                cmin[cc] = fminf(cmin[cc], d2);
            } else if (!diag || ri != ci) {
                h += diag ? 1 : 2;
            }
        }
        rmin = fminf(rmin, __shfl_xor_sync(0xffffffffu, rmin, 1));
        rmin = fminf(rmin, __shfl_xor_sync(0xffffffffu, rmin, 2));
        rmin = fminf(rmin, __shfl_xor_sync(0xffffffffu, rmin, 4));
        rmin = fminf(rmin, __shfl_xor_sync(0xffffffffu, rmin, 8));
        if (tx == 0 && rmin < CUDART_INF_F)
            atomicMin(&g_minneg[rowBase + ri], __float_as_uint(rmin));
    }

    if (!diag) {
#pragma unroll
        for (int cc = 0; cc < 8; cc++) {
            if (cmin[cc] < CUDART_INF_F) {
                const int ci = 2 * (tx + 16 * (cc >> 1)) + (cc & 1);
                atomicMin(&s_cmin[ci], __float_as_uint(cmin[cc]));
            }
        }
    }

    unsigned lbase = 0u;
    if (h) lbase = atomicAdd(&s_cnt, (unsigned)h);
    __syncthreads();
    if (tid == 0) s_base = s_cnt ? atomicAdd(&g_paircnt, s_cnt) : 0u;
    if (!diag && tid < 128 && s_cmin[tid] != INF_BITS)
        atomicMin(&g_minneg[colBase + tid], s_cmin[tid]);
    __syncthreads();

    if (h) {
        unsigned p = s_base + lbase;
#pragma unroll
        for (int rr = 0; rr < 8; rr++) {
            const int ri = ty * 8 + rr;
            const int cr = s_cr[ri];
#pragma unroll
            for (int cc = 0; cc < 8; cc++) {
                const int ci = 2 * (tx + 16 * (cc >> 1)) + (cc & 1);
                if (cr == s_cc[ci] && (!diag || ri != ci)) {
                    unsigned db = __float_as_uint(dist[rr][cc]);
                    if (p < PAIR_CAP)
                        g_pair[p] = ((ull)(unsigned)(rowBase + ri) << 32) | db;
                    p++;
                    if (!diag) {
                        if (p < PAIR_CAP)
                            g_pair[p] = ((ull)(unsigned)(colBase + ci) << 32) | db;
                        p++;
                    }
                }
            }
        }
    }
#endif
}

// ---------------- kernel 3: hinge over positive pairs (d2 -> d) ------------
__global__ void pair_kernel() {
    unsigned n = g_paircnt;
    if (n > PAIR_CAP) n = PAIR_CAP;
    const int tid = threadIdx.x;
    double t = 0.0;
    ull c = 0ull;
    for (unsigned i = blockIdx.x * blockDim.x + tid; i < n; i += gridDim.x * blockDim.x) {
        ull pk = g_pair[i];
        int r = (int)(pk >> 32);
        unsigned mb = g_minneg[r];
        if (mb < INF_BITS) {  // has_neg
            float d  = sqrtf(__uint_as_float((unsigned)pk));
            float mn = sqrtf(__uint_as_float(mb));
            float tl = d - mn + MARGIN;
            if (tl > 0.0f) t += (double)tl;
            c++;
        }
    }
    __shared__ double st[256];
    __shared__ ull    sc[256];
    st[tid] = t; sc[tid] = c;
    __syncthreads();
    for (int s = 128; s; s >>= 1) {
        if (tid < s) { st[tid] += st[tid + s]; sc[tid] += sc[tid + s]; }
        __syncthreads();
    }
    if (tid == 0) {
        if (st[0] != 0.0) atomicAdd(&g_total, st[0]);
        if (sc[0])        atomicAdd(&g_valid, sc[0]);
    }
}

// ---------------- kernel 4: finalize ----------------
__global__ void final_kernel(float* __restrict__ out) {
    out[0] = g_valid ? (float)(g_total / (double)g_valid) : 0.0f;
}

// ---------------- launch ----------------
extern "C" void kernel_launch(void* const* d_in, const int* in_sizes, int n_in,
                              void* d_out, int out_size) {
    const float* emb  = (const float*)d_in[0];
    const int*   comm = (const int*)d_in[1];
    float*       out  = (float*)d_out;

    init_kernel<<<1, 256>>>(comm);
    sqn_kernel<<<N_NODES / 8, 256>>>(emb);
    split_kernel<<<(N_NODES * EMBED_DIM / 4) / 256, 256>>>(emb);

    cudaFuncSetAttribute(gemm_kernel, cudaFuncAttributeMaxDynamicSharedMemorySize, SMEM_BYTES);
    gemm_kernel<<<NBLOCKS, 256, SMEM_BYTES>>>(emb);

    pair_kernel<<<512, 256>>>();
    final_kernel<<<1, 1>>>(out);
}

// round 16
// speedup vs baseline: 4.0605x; 1.0519x over previous
#include <cuda_runtime.h>
#include <cuda_bf16.h>
#include <math_constants.h>
#include <cstdint>

typedef unsigned long long ull;

#define N_NODES   8192
#define EMBED_DIM 128
#define MARGIN    1.0f
#define NB        (N_NODES / 128)
#define NBLOCKS   (NB * (NB + 1) / 2)      // 2080 upper-triangle tiles
#define PAIR_CAP  (1u << 21)
#define TILE_B    (128 * 128 * 2)          // one 128x128 bf16 tile = 32KB
#define SMEM_BYTES (2 * TILE_B + 1024)     // B_hi + B_lo + alignment slack

#define MMA_IDESC 0x8200490u               // kind::f16: F32 acc, bf16 a/b, M=128, N=128
#define INF_BITS  0x7f800000u
#define TMEM_A_HI 0
#define TMEM_A_LO 64
#define TMEM_D    128
#define TMEM_COLS 256

#if defined(__CUDA_ARCH__) && (defined(__CUDA_ARCH_FEAT_SM103_ALL) || defined(__CUDA_ARCH_FEAT_SM100_ALL) || defined(__CUDA_ARCH_FEAT_SM101_ALL))
#define HAS_TCGEN05 1
#else
#define HAS_TCGEN05 0
#endif

// ---------------- device scratch ----------------
__device__ int            g_comm[N_NODES];
__device__ float          g_sqn[N_NODES];
__device__ unsigned       g_minneg[N_NODES];     // bits of min negative d^2
__device__ unsigned       g_paircnt;
__device__ ull            g_pair[PAIR_CAP];      // hi32=anchor row, lo32=d^2 bits
__device__ double         g_total;
__device__ ull            g_valid;
__device__ __nv_bfloat16  g_hi[N_NODES * EMBED_DIM];
__device__ __nv_bfloat16  g_lo[N_NODES * EMBED_DIM];

// ---------------- kernel 0: dtype probe + convert + init ----------------
__global__ void init_kernel(const int* __restrict__ comm_raw) {
    __shared__ int s_or;
    int tid = threadIdx.x;
    if (tid == 0) s_or = 0;
    __syncthreads();
    int acc = 0;
    for (int i = tid; i < N_NODES / 2; i += blockDim.x)
        acc |= comm_raw[2 * i + 1];
    if (acc) atomicOr(&s_or, 1);
    __syncthreads();
    bool is64 = (s_or == 0);
    const long long* c64 = (const long long*)comm_raw;
    for (int i = tid; i < N_NODES; i += blockDim.x) {
        g_comm[i]   = is64 ? (int)c64[i] : comm_raw[i];
        g_minneg[i] = INF_BITS;
    }
    if (tid == 0) { g_paircnt = 0u; g_total = 0.0; g_valid = 0ull; }
}

// ---------------- kernel 1: squared norms ----------------
__global__ void sqn_kernel(const float* __restrict__ emb) {
    int warp = threadIdx.x >> 5, lane = threadIdx.x & 31;
    int row = blockIdx.x * 8 + warp;
    if (row >= N_NODES) return;
    const float* p = emb + (size_t)row * EMBED_DIM;
    float s = 0.f;
#pragma unroll
    for (int k = lane; k < EMBED_DIM; k += 32) { float v = p[k]; s = fmaf(v, v, s); }
#pragma unroll
    for (int o = 16; o; o >>= 1) s += __shfl_xor_sync(0xffffffffu, s, o);
    if (lane == 0) g_sqn[row] = s;
}

// ---------------- kernel 1b: bf16 hi/lo split ----------------
__global__ void split_kernel(const float* __restrict__ emb) {
    int i = blockIdx.x * blockDim.x + threadIdx.x;   // one float4 per thread
    float4 v = ((const float4*)emb)[i];
    __nv_bfloat16 h0 = __float2bfloat16(v.x), h1 = __float2bfloat16(v.y);
    __nv_bfloat16 h2 = __float2bfloat16(v.z), h3 = __float2bfloat16(v.w);
    __nv_bfloat16 l0 = __float2bfloat16(v.x - __bfloat162float(h0));
    __nv_bfloat16 l1 = __float2bfloat16(v.y - __bfloat162float(h1));
    __nv_bfloat16 l2 = __float2bfloat16(v.z - __bfloat162float(h2));
    __nv_bfloat16 l3 = __float2bfloat16(v.w - __bfloat162float(h3));
    ((__nv_bfloat162*)g_hi)[2 * i]     = __nv_bfloat162(h0, h1);
    ((__nv_bfloat162*)g_hi)[2 * i + 1] = __nv_bfloat162(h2, h3);
    ((__nv_bfloat162*)g_lo)[2 * i]     = __nv_bfloat162(l0, l1);
    ((__nv_bfloat162*)g_lo)[2 * i + 1] = __nv_bfloat162(l2, l3);
}

#if HAS_TCGEN05
// ================= tcgen05 helpers (sm_103a targets only) =================
__device__ __forceinline__ uint32_t smem_u32(const void* p) {
    uint32_t a;
    asm("{ .reg .u64 t; cvta.to.shared.u64 t, %1; cvt.u32.u64 %0, t; }" : "=r"(a) : "l"(p));
    return a;
}
__device__ __forceinline__ uint32_t elect_one() {
    uint32_t p;
    asm volatile("{ .reg .pred p; elect.sync _|p, 0xFFFFFFFF; selp.b32 %0, 1, 0, p; }" : "=r"(p));
    return p;
}
#define TC_ALLOC(sm, n)   asm volatile("tcgen05.alloc.cta_group::1.sync.aligned.shared::cta.b32 [%0], %1;" :: "r"(sm), "r"(n) : "memory")
#define TC_DEALLOC(t, n)  asm volatile("tcgen05.dealloc.cta_group::1.sync.aligned.b32 %0, %1;" :: "r"(t), "r"(n))
#define TC_RELINQ()       asm volatile("tcgen05.relinquish_alloc_permit.cta_group::1.sync.aligned;")
#define TC_COMMIT(mb)     asm volatile("tcgen05.commit.cta_group::1.mbarrier::arrive::one.shared::cluster.b64 [%0];" :: "r"(mb) : "memory")
#define TC_WAIT_LD()      asm volatile("tcgen05.wait::ld.sync.aligned;" ::: "memory")
#define TC_WAIT_ST()      asm volatile("tcgen05.wait::st.sync.aligned;" ::: "memory")
#define TC_FENCE_BEFORE() asm volatile("tcgen05.fence::before_thread_sync;" ::: "memory")
#define TC_FENCE_AFTER()  asm volatile("tcgen05.fence::after_thread_sync;" ::: "memory")
#define MB_INIT(mb, n)    asm volatile("mbarrier.init.shared.b64 [%0], %1;" :: "r"(mb), "r"(n) : "memory")
#define FENCE_ASYNC()     asm volatile("fence.proxy.async.shared::cta;" ::: "memory")

__device__ __forceinline__ void mbar_wait0(uint32_t mb) {
    asm volatile(
        "{\n\t.reg .pred P1;\n\t"
        "WL_%=:\n\t"
        "mbarrier.try_wait.parity.acquire.cta.shared::cta.b64 P1, [%0], 0, 0x989680;\n\t"
        "@P1 bra.uni WD_%=;\n\t"
        "bra.uni WL_%=;\n\t"
        "WD_%=:\n\t}"
        :: "r"(mb) : "memory");
}
// TS-mode MMA: A in TMEM ([%1]), B via smem descriptor
__device__ __forceinline__ void mma_f16_ts(uint32_t d, uint32_t a_tmem, uint64_t b, uint32_t idesc, uint32_t acc) {
    asm volatile(
        "{\n\t.reg .pred p;\n\tsetp.ne.u32 p, %5, 0;\n\t"
        "tcgen05.mma.cta_group::1.kind::f16 [%0], [%1], %2, %3, {%4, %4, %4, %4}, p;\n\t}"
        :: "r"(d), "r"(a_tmem), "l"(b), "r"(idesc), "r"(0u), "r"(acc) : "memory");
}
#define LDTM_X32(r, ta) \
    asm volatile("tcgen05.ld.sync.aligned.32x32b.x32.b32 " \
        "{%0,%1,%2,%3,%4,%5,%6,%7,%8,%9,%10,%11,%12,%13,%14,%15," \
        "%16,%17,%18,%19,%20,%21,%22,%23,%24,%25,%26,%27,%28,%29,%30,%31}, [%32];" \
        : "=r"((r)[0]),"=r"((r)[1]),"=r"((r)[2]),"=r"((r)[3]),"=r"((r)[4]),"=r"((r)[5]),"=r"((r)[6]),"=r"((r)[7]), \
          "=r"((r)[8]),"=r"((r)[9]),"=r"((r)[10]),"=r"((r)[11]),"=r"((r)[12]),"=r"((r)[13]),"=r"((r)[14]),"=r"((r)[15]), \
          "=r"((r)[16]),"=r"((r)[17]),"=r"((r)[18]),"=r"((r)[19]),"=r"((r)[20]),"=r"((r)[21]),"=r"((r)[22]),"=r"((r)[23]), \
          "=r"((r)[24]),"=r"((r)[25]),"=r"((r)[26]),"=r"((r)[27]),"=r"((r)[28]),"=r"((r)[29]),"=r"((r)[30]),"=r"((r)[31]) \
        : "r"(ta))
#define STTM_X64(ta, r) \
    asm volatile("tcgen05.st.sync.aligned.32x32b.x64.b32 [%0], " \
        "{%1,%2,%3,%4,%5,%6,%7,%8,%9,%10,%11,%12,%13,%14,%15,%16," \
        "%17,%18,%19,%20,%21,%22,%23,%24,%25,%26,%27,%28,%29,%30,%31,%32," \
        "%33,%34,%35,%36,%37,%38,%39,%40,%41,%42,%43,%44,%45,%46,%47,%48," \
        "%49,%50,%51,%52,%53,%54,%55,%56,%57,%58,%59,%60,%61,%62,%63,%64};" \
        :: "r"(ta), \
           "r"((r)[0]),"r"((r)[1]),"r"((r)[2]),"r"((r)[3]),"r"((r)[4]),"r"((r)[5]),"r"((r)[6]),"r"((r)[7]), \
           "r"((r)[8]),"r"((r)[9]),"r"((r)[10]),"r"((r)[11]),"r"((r)[12]),"r"((r)[13]),"r"((r)[14]),"r"((r)[15]), \
           "r"((r)[16]),"r"((r)[17]),"r"((r)[18]),"r"((r)[19]),"r"((r)[20]),"r"((r)[21]),"r"((r)[22]),"r"((r)[23]), \
           "r"((r)[24]),"r"((r)[25]),"r"((r)[26]),"r"((r)[27]),"r"((r)[28]),"r"((r)[29]),"r"((r)[30]),"r"((r)[31]), \
           "r"((r)[32]),"r"((r)[33]),"r"((r)[34]),"r"((r)[35]),"r"((r)[36]),"r"((r)[37]),"r"((r)[38]),"r"((r)[39]), \
           "r"((r)[40]),"r"((r)[41]),"r"((r)[42]),"r"((r)[43]),"r"((r)[44]),"r"((r)[45]),"r"((r)[46]),"r"((r)[47]), \
           "r"((r)[48]),"r"((r)[49]),"r"((r)[50]),"r"((r)[51]),"r"((r)[52]),"r"((r)[53]),"r"((r)[54]),"r"((r)[55]), \
           "r"((r)[56]),"r"((r)[57]),"r"((r)[58]),"r"((r)[59]),"r"((r)[60]),"r"((r)[61]),"r"((r)[62]),"r"((r)[63]) \
        : "memory")

// SW128 K-major descriptor base: layout=SW128, version=1(Blackwell), SBO=64, LBO=1
static constexpr uint64_t DESC_BASE =
    (uint64_t(2) << 61) | (uint64_t(1) << 46) | (uint64_t(64) << 32) | (uint64_t(1) << 16);
__device__ __forceinline__ uint64_t make_desc(uint32_t addr) {
    return DESC_BASE | ((uint64_t)(addr >> 4) & 0x3FFF);
}

// B tile loader: global bf16 -> blocked SW128 atom layout, 128 threads
// dst MUST be 1024B-aligned (absolute-address swizzle).
__device__ __forceinline__ void load_tile128(const __nv_bfloat16* __restrict__ src,
                                             char* dst, int nodeBase, int t) {
#pragma unroll
    for (int it = 0; it < 16; it++) {
        int ch = t + 128 * it;              // 2048 chunks of 16B
        int r = ch >> 4, q = ch & 15;
        uint4 v = *(const uint4*)(src + (size_t)(nodeBase + r) * EMBED_DIM + q * 8);
        int bo = ((r >> 3) + ((q >> 3) << 4)) * 1024 + (r & 7) * 128 + (q & 7) * 16;
        *(uint4*)(dst + (bo ^ ((bo >> 3) & 0x70))) = v;
    }
}
#else
// ================= packed f32x2 helpers (fallback path) =================
__device__ __forceinline__ void upk2f(float& x, float& y, ull v) {
    asm("mov.b64 {%0, %1}, %2;" : "=f"(x), "=f"(y) : "l"(v));
}
__device__ __forceinline__ ull pk2f(float x, float y) {
    ull r;
    asm("mov.b64 %0, {%1, %2};" : "=l"(r) : "f"(x), "f"(y));
    return r;
}
__device__ __forceinline__ void fma2f(ull& c, ull a, ull b) {
    asm("fma.rn.f32x2 %0, %1, %2, %3;" : "=l"(c) : "l"(a), "l"(b), "l"(c));
}
#endif

// ---------------- kernel 2: fused Gram / d2 / min-neg / positives ----------
__global__ __launch_bounds__(256, 2) void gemm_kernel(const float* __restrict__ emb) {
    __shared__ int      s_cr[128], s_cc[128];
    __shared__ float    s_qr[128], s_qc[128];
    __shared__ unsigned s_cmin[128];
    __shared__ unsigned s_cnt, s_base;

    const int tid = threadIdx.x;

    // triangular block decode (row-major over upper triangle)
    int by = 0, rem = blockIdx.x;
    while (rem >= NB - by) { rem -= NB - by; by++; }
    const int bx = by + rem;
    const int rowBase = by * 128;
    const int colBase = bx * 128;
    const bool diag = (bx == by);

#if HAS_TCGEN05
    extern __shared__ char smraw[];
    // SW128 swizzle depends on absolute address bits — 1024B-align the tiles.
    char* sm = (char*)(((uintptr_t)smraw + 1023) & ~(uintptr_t)1023);
    char* Bhi = sm;
    char* Blo = sm + TILE_B;

    __shared__ uint2    s_qcc[128];          // {sqn bits, community} per column
    __shared__ unsigned s_rmin_t[2][128];    // per-half row-min slots (no atomics)
    __shared__ unsigned s_cmin_t[4][128];    // per-warp-slot col-min slots (no atomics)
    __shared__ uint32_t s_tmem;
    __shared__ ull      s_mbar;

    const int w    = tid >> 5;
    const int lane = tid & 31;
    const uint32_t mbar_addr = smem_u32(&s_mbar);
    const uint32_t tptr_addr = smem_u32(&s_tmem);

    if (w == 0) TC_ALLOC(tptr_addr, TMEM_COLS);
    if (tid == 0) MB_INIT(mbar_addr, 1);

    if (tid < 128) {
        s_cr[tid] = g_comm[rowBase + tid];
        s_qr[tid] = g_sqn[rowBase + tid];
    } else {
        int t = tid - 128;
        s_qcc[t] = make_uint2(__float_as_uint(g_sqn[colBase + t]),
                              (unsigned)g_comm[colBase + t]);
    }
    __syncthreads();                 // s_tmem visible to all
    const uint32_t tmem = s_tmem;

    if (tid < 128) {
        // ---- A rows -> TMEM (hi at cols 0..63, lo at 64..127) ----
        const uint32_t aw_off = (uint32_t)(tid >> 5) << 21;
        uint32_t a[64];
        const uint4* srch = (const uint4*)(g_hi + (size_t)(rowBase + tid) * EMBED_DIM);
#pragma unroll
        for (int q = 0; q < 16; q++) {
            uint4 v = srch[q];
            a[4*q] = v.x; a[4*q+1] = v.y; a[4*q+2] = v.z; a[4*q+3] = v.w;
        }
        STTM_X64(tmem + TMEM_A_HI + aw_off, a);
        const uint4* srcl = (const uint4*)(g_lo + (size_t)(rowBase + tid) * EMBED_DIM);
#pragma unroll
        for (int q = 0; q < 16; q++) {
            uint4 v = srcl[q];
            a[4*q] = v.x; a[4*q+1] = v.y; a[4*q+2] = v.z; a[4*q+3] = v.w;
        }
        STTM_X64(tmem + TMEM_A_LO + aw_off, a);
        TC_WAIT_ST();
    } else {
        // ---- B tiles -> smem (blocked SW128 atoms) ----
        load_tile128(g_hi, Bhi, colBase, tid - 128);
        load_tile128(g_lo, Blo, colBase, tid - 128);
    }
    TC_FENCE_BEFORE();
    FENCE_ASYNC();
    __syncthreads();
    if (w == 0) TC_RELINQ();

    if (w == 0 && elect_one()) {
        TC_FENCE_AFTER();
        uint64_t bhid = make_desc(smem_u32(Bhi));
        uint64_t blod = make_desc(smem_u32(Blo));
        // terms: Ahi*Bhi + Ahi*Blo + Alo*Bhi  (lo*lo dropped, ~4e-5 abs on dot)
        uint32_t aoff[3] = { TMEM_A_HI, TMEM_A_HI, TMEM_A_LO };
        uint64_t bdsc[3] = { bhid, blod, bhid };
        uint32_t acc = 0;
#pragma unroll
        for (int t = 0; t < 3; t++) {
#pragma unroll
            for (int ks = 0; ks < 8; ks++) {
                uint64_t ko = (ks < 4) ? (uint64_t)(2 * ks) : (uint64_t)(1024 + 2 * (ks - 4));
                mma_f16_ts(tmem + TMEM_D, tmem + aoff[t] + ks * 8, bdsc[t] + ko, MMA_IDESC, acc);
                acc = 1;
            }
        }
        TC_COMMIT(mbar_addr);
    }

    mbar_wait0(mbar_addr);
    TC_FENCE_AFTER();

    // ---- epilogue: warp w -> rows (w&3)*32.., cols (w>>2)*64.., two 32-col chunks ----
    // All du[] indices compile-time; all smem reductions via private slots (no ATOMS).
    const int rl     = (w & 3) * 32 + lane;
    const int cbase0 = (w >> 2) * 64;
    const uint32_t dw_off = (uint32_t)(w & 3) << 21;

    const float sqr = s_qr[rl];
    const int   cr  = s_cr[rl];
    float rmin2 = CUDART_INF_F;

#pragma unroll
    for (int ch = 0; ch < 2; ch++) {
        const int cb = cbase0 + 32 * ch;
        uint32_t du[32];
        LDTM_X32(du, tmem + TMEM_D + dw_off + cb);
        TC_WAIT_LD();

        unsigned nm = 0u, pm = 0u;
#pragma unroll
        for (int j = 0; j < 32; j++) {
            const int ci = cb + j;
            uint2 qcc = s_qcc[ci];            // broadcast LDS.64: {qc bits, cc}
            float d2 = fmaxf(fmaf(-2.0f, __uint_as_float(du[j]),
                                  sqr + __uint_as_float(qcc.x)), 0.0f);
            du[j] = __float_as_uint(d2);
            if (cr != (int)qcc.y) {
                nm |= 1u << j;
                rmin2 = fminf(rmin2, d2);
            } else if (!diag || rl != ci) {
                pm |= 1u << j;
            }
        }

        if (!diag) {
            // column-min across warp rows: REDUX + plain store to private slot
#pragma unroll
            for (int j = 0; j < 32; j++) {
                unsigned v = ((nm >> j) & 1u) ? du[j] : INF_BITS;
                v = __reduce_min_sync(0xffffffffu, v);
                if (lane == 0) s_cmin_t[w & 3][cb + j] = v;
            }
        }

        // ---- pair emission: warp exclusive scan + one global atomic ----
        unsigned h = (unsigned)__popc(pm);
        if (!diag) h *= 2u;
        unsigned incl = h;
#pragma unroll
        for (int d = 1; d < 32; d <<= 1) {
            unsigned t = __shfl_up_sync(0xffffffffu, incl, d);
            if (lane >= d) incl += t;
        }
        unsigned tot = __shfl_sync(0xffffffffu, incl, 31);
        unsigned base = 0u;
        if (tot) {
            if (lane == 31) base = atomicAdd(&g_paircnt, tot);
            base = __shfl_sync(0xffffffffu, base, 31);
        }
        unsigned p = base + incl - h;
#pragma unroll
        for (int j = 0; j < 32; j++) {
            if ((pm >> j) & 1u) {
                unsigned db = du[j];
                if (p < PAIR_CAP) g_pair[p] = ((ull)(unsigned)(rowBase + rl) << 32) | db;
                p++;
                if (!diag) {
                    if (p < PAIR_CAP) g_pair[p] = ((ull)(unsigned)(colBase + cb + j) << 32) | db;
                    p++;
                }
            }
        }
    }

    s_rmin_t[w >> 2][rl] = __float_as_uint(rmin2);   // plain store, disjoint writers
    __syncthreads();

    // combine passes (uint compare valid: non-negative float bits are order-preserving)
    if (tid < 128) {
        unsigned v = min(s_rmin_t[0][tid], s_rmin_t[1][tid]);
        if (v != INF_BITS) atomicMin(&g_minneg[rowBase + tid], v);
    } else if (!diag) {
        int t = tid - 128;
        unsigned v = min(min(s_cmin_t[0][t], s_cmin_t[1][t]),
                         min(s_cmin_t[2][t], s_cmin_t[3][t]));
        if (v != INF_BITS) atomicMin(&g_minneg[colBase + t], v);
    }

    __syncthreads();
    if (w == 0) TC_DEALLOC(tmem, TMEM_COLS);

#else  // ---------------- FFMA2 fallback body (compile-only on plain PTX) ----
    extern __shared__ float smf[];
    float* As = smf;
    float* Bs = smf + 128 * 128;

    if (tid < 128) {
        s_cr[tid] = g_comm[rowBase + tid];
        s_qr[tid] = g_sqn[rowBase + tid];
        s_cmin[tid] = INF_BITS;
    } else {
        int t = tid - 128;
        s_cc[t] = g_comm[colBase + t];
        s_qc[t] = g_sqn[colBase + t];
    }
    if (tid == 0) s_cnt = 0u;

    {
        int r = tid & 127;
        const float4* src = (const float4*)(emb + (size_t)((tid < 128 ? rowBase : colBase) + r) * EMBED_DIM);
        float* dst = (tid < 128) ? As : Bs;
#pragma unroll
        for (int q = 0; q < 32; q++) {
            float4 v = src[q];
            int k = q * 4;
            dst[(k + 0) * 128 + r] = v.x; dst[(k + 1) * 128 + r] = v.y;
            dst[(k + 2) * 128 + r] = v.z; dst[(k + 3) * 128 + r] = v.w;
        }
    }
    __syncthreads();

    const int tx = tid & 15;
    const int ty = tid >> 4;

    ull acc[8][4];
#pragma unroll
    for (int r = 0; r < 8; r++)
#pragma unroll
        for (int c = 0; c < 4; c++) acc[r][c] = 0ull;

#pragma unroll 4
    for (int k = 0; k < 128; k++) {
        const float* ap = As + k * 128 + ty * 8;
        const float* bp = Bs + k * 128;
        ull b0 = *(const ull*)(bp + 2 * tx);
        ull b1 = *(const ull*)(bp + 2 * tx + 32);
        ull b2 = *(const ull*)(bp + 2 * tx + 64);
        ull b3 = *(const ull*)(bp + 2 * tx + 96);
        float4 a0 = *(const float4*)ap;
        float4 a1 = *(const float4*)(ap + 4);
        float ar[8] = {a0.x, a0.y, a0.z, a0.w, a1.x, a1.y, a1.z, a1.w};
#pragma unroll
        for (int rr = 0; rr < 8; rr++) {
            ull a2 = pk2f(ar[rr], ar[rr]);
            fma2f(acc[rr][0], a2, b0);
            fma2f(acc[rr][1], a2, b1);
            fma2f(acc[rr][2], a2, b2);
            fma2f(acc[rr][3], a2, b3);
        }
    }

    float dist[8][8];
    float cmin[8];
#pragma unroll
    for (int cc = 0; cc < 8; cc++) cmin[cc] = CUDART_INF_F;
    int h = 0;
#pragma unroll
    for (int rr = 0; rr < 8; rr++) {
        const int ri  = ty * 8 + rr;
        const float sqr = s_qr[ri];
        const int   cr  = s_cr[ri];
        float rmin = CUDART_INF_F;
#pragma unroll
        for (int cc = 0; cc < 8; cc++) {
            const int ci = 2 * (tx + 16 * (cc >> 1)) + (cc & 1);
            float lo, hi;
            upk2f(lo, hi, acc[rr][cc >> 1]);
            float dot = (cc & 1) ? hi : lo;
            float d2 = fmaxf(sqr + s_qc[ci] - 2.0f * dot, 0.0f);
            dist[rr][cc] = d2;
            if (cr != s_cc[ci]) {
                rmin = fminf(rmin, d2);
                cmin[cc] = fminf(cmin[cc], d2);
            } else if (!diag || ri != ci) {
                h += diag ? 1 : 2;
            }
        }
        rmin = fminf(rmin, __shfl_xor_sync(0xffffffffu, rmin, 1));
        rmin = fminf(rmin, __shfl_xor_sync(0xffffffffu, rmin, 2));
        rmin = fminf(rmin, __shfl_xor_sync(0xffffffffu, rmin, 4));
        rmin = fminf(rmin, __shfl_xor_sync(0xffffffffu, rmin, 8));
        if (tx == 0 && rmin < CUDART_INF_F)
            atomicMin(&g_minneg[rowBase + ri], __float_as_uint(rmin));
    }

    if (!diag) {
#pragma unroll
        for (int cc = 0; cc < 8; cc++) {
            if (cmin[cc] < CUDART_INF_F) {
                const int ci = 2 * (tx + 16 * (cc >> 1)) + (cc & 1);
                atomicMin(&s_cmin[ci], __float_as_uint(cmin[cc]));
            }
        }
    }

    unsigned lbase = 0u;
    if (h) lbase = atomicAdd(&s_cnt, (unsigned)h);
    __syncthreads();
    if (tid == 0) s_base = s_cnt ? atomicAdd(&g_paircnt, s_cnt) : 0u;
    if (!diag && tid < 128 && s_cmin[tid] != INF_BITS)
        atomicMin(&g_minneg[colBase + tid], s_cmin[tid]);
    __syncthreads();

    if (h) {
        unsigned p = s_base + lbase;
#pragma unroll
        for (int rr = 0; rr < 8; rr++) {
            const int ri = ty * 8 + rr;
            const int cr = s_cr[ri];
#pragma unroll
            for (int cc = 0; cc < 8; cc++) {
                const int ci = 2 * (tx + 16 * (cc >> 1)) + (cc & 1);
                if (cr == s_cc[ci] && (!diag || ri != ci)) {
                    unsigned db = __float_as_uint(dist[rr][cc]);
                    if (p < PAIR_CAP)
                        g_pair[p] = ((ull)(unsigned)(rowBase + ri) << 32) | db;
                    p++;
                    if (!diag) {
                        if (p < PAIR_CAP)
                            g_pair[p] = ((ull)(unsigned)(colBase + ci) << 32) | db;
                        p++;
                    }
                }
            }
        }
    }
#endif
}

// ---------------- kernel 3: hinge over positive pairs (d2 -> d) ------------
__global__ void pair_kernel() {
    unsigned n = g_paircnt;
    if (n > PAIR_CAP) n = PAIR_CAP;
    const int tid = threadIdx.x;
    double t = 0.0;
    ull c = 0ull;
    for (unsigned i = blockIdx.x * blockDim.x + tid; i < n; i += gridDim.x * blockDim.x) {
        ull pk = g_pair[i];
        int r = (int)(pk >> 32);
        unsigned mb = g_minneg[r];
        if (mb < INF_BITS) {  // has_neg
            float d  = sqrtf(__uint_as_float((unsigned)pk));
            float mn = sqrtf(__uint_as_float(mb));
            float tl = d - mn + MARGIN;
            if (tl > 0.0f) t += (double)tl;
            c++;
        }
    }
    __shared__ double st[256];
    __shared__ ull    sc[256];
    st[tid] = t; sc[tid] = c;
    __syncthreads();
    for (int s = 128; s; s >>= 1) {
        if (tid < s) { st[tid] += st[tid + s]; sc[tid] += sc[tid + s]; }
        __syncthreads();
    }
    if (tid == 0) {
        if (st[0] != 0.0) atomicAdd(&g_total, st[0]);
        if (sc[0])        atomicAdd(&g_valid, sc[0]);
    }
}

// ---------------- kernel 4: finalize ----------------
__global__ void final_kernel(float* __restrict__ out) {
    out[0] = g_valid ? (float)(g_total / (double)g_valid) : 0.0f;
}

// ---------------- launch ----------------
extern "C" void kernel_launch(void* const* d_in, const int* in_sizes, int n_in,
                              void* d_out, int out_size) {
    const float* emb  = (const float*)d_in[0];
    const int*   comm = (const int*)d_in[1];
    float*       out  = (float*)d_out;

    init_kernel<<<1, 256>>>(comm);
    sqn_kernel<<<N_NODES / 8, 256>>>(emb);
    split_kernel<<<(N_NODES * EMBED_DIM / 4) / 256, 256>>>(emb);

    cudaFuncSetAttribute(gemm_kernel, cudaFuncAttributeMaxDynamicSharedMemorySize, SMEM_BYTES);
    gemm_kernel<<<NBLOCKS, 256, SMEM_BYTES>>>(emb);

    pair_kernel<<<512, 256>>>();
    final_kernel<<<1, 1>>>(out);
}